// round 12
// baseline (speedup 1.0000x reference)
#include <cuda_runtime.h>
#include <math.h>
#include <stdint.h>

#define S_    4096
#define D_    768
#define H_    12
#define HD_   64
#define NCLS_ 64
#define FF_   3072
#define WIN_  256
#define LAYERS_ 2

// ---------------- scratch (static device globals; no allocation) ----------------
__device__ float g_h  [S_*D_];
__device__ float g_q  [S_*D_];
__device__ float g_k  [S_*D_];
__device__ float g_v  [S_*D_];
__device__ float g_kg [S_*D_];
__device__ float g_vg [S_*D_];
__device__ float g_out[S_*D_];
__device__ float g_tmp[S_*D_];
__device__ float g_ff [S_*FF_];
__device__ float g_hg [NCLS_*D_];
__device__ float g_qg [NCLS_*D_];
__device__ int   g_glb[S_];

static __device__ __forceinline__ uint32_t smem_u32(const void* p) {
    uint32_t a;
    asm("{ .reg .u64 t; cvta.to.shared.u64 t, %1; cvt.u32.u64 %0, t; }" : "=r"(a) : "l"(p));
    return a;
}
#define CP16(dst, src) \
    asm volatile("cp.async.cg.shared.global [%0], [%1], 16;" :: "r"(dst), "l"(src))
#define CP_COMMIT() asm volatile("cp.async.commit_group;" ::: "memory")
#define CP_WAIT0()  asm volatile("cp.async.wait_group 0;" ::: "memory")

// ---------------- fp32 SGEMM: C = A(MxK) @ B(KxN) + bias, optional gelu ----------------
// 128x128 tile, BK=32, cp.async double-buffered (no LDG/STS in issue stream).
// A kept row-major [m][k] in smem; fragments loaded as float4 along k.
#define BK_     32
#define SAK_    36                    /* A smem row stride (floats) */
#define SBN_    132                   /* B smem row stride (floats) */
#define ASTAGE_ (128 * SAK_)          /* 4608 floats */
#define BSTAGE_ (BK_ * SBN_)          /* 4224 floats */
#define GEMM_SMEM ((ASTAGE_ + BSTAGE_) * 2 * 4)   /* 70656 bytes */

#define GEMM_COMPUTE_(as, bs)                                                        \
    _Pragma("unroll")                                                                \
    for (int kg = 0; kg < 8; kg++) {                                                 \
        float a4[8][4];                                                              \
        _Pragma("unroll")                                                            \
        for (int i_ = 0; i_ < 8; i_++)                                               \
            *reinterpret_cast<float4*>(a4[i_]) =                                     \
                *reinterpret_cast<const float4*>((as) + (ty * 8 + i_) * SAK_ + kg * 4); \
        _Pragma("unroll")                                                            \
        for (int kk = 0; kk < 4; kk++) {                                             \
            float b[8];                                                              \
            *reinterpret_cast<float4*>(b) =                                          \
                *reinterpret_cast<const float4*>((bs) + (kg * 4 + kk) * SBN_ + tx * 8); \
            *reinterpret_cast<float4*>(b + 4) =                                      \
                *reinterpret_cast<const float4*>((bs) + (kg * 4 + kk) * SBN_ + tx * 8 + 4); \
            _Pragma("unroll")                                                        \
            for (int i_ = 0; i_ < 8; i_++)                                           \
                _Pragma("unroll")                                                    \
                for (int j_ = 0; j_ < 8; j_++)                                       \
                    acc[i_][j_] = fmaf(a4[i_][kk], b[j_], acc[i_][j_]);              \
        }                                                                            \
    }

#define GEMM_LOADSTAGE_(sidx, k0)                                                    \
    {                                                                                \
        const uint32_t ad = asu + (uint32_t)(((sidx) * ASTAGE_ + arow * SAK_ + acol) * 4); \
        const float* ap = Apt + (k0);                                                \
        _Pragma("unroll")                                                            \
        for (int c_ = 0; c_ < 4; c_++) CP16(ad + c_ * 16, ap + c_ * 4);              \
        const uint32_t bd = bsu + (uint32_t)(((sidx) * BSTAGE_ + brow * SBN_ + bcol) * 4); \
        const float* bp = Bpt + (size_t)(k0) * N;                                    \
        _Pragma("unroll")                                                            \
        for (int c_ = 0; c_ < 4; c_++) CP16(bd + c_ * 16, bp + c_ * 4);              \
        CP_COMMIT();                                                                 \
    }

__global__ __launch_bounds__(256, 2) void sgemm_kernel(
    const float* __restrict__ A, const float* __restrict__ B,
    const float* __restrict__ bias, float* __restrict__ C,
    int M, int N, int K, int act)
{
    extern __shared__ float smem[];
    float* As0 = smem;                   // [2][ASTAGE_]
    float* Bs0 = smem + 2 * ASTAGE_;     // [2][BSTAGE_]
    const uint32_t asu = smem_u32(As0);
    const uint32_t bsu = smem_u32(Bs0);

    const int tid = threadIdx.x;
    const int tx = tid & 15;
    const int ty = tid >> 4;
    const int blockRow = blockIdx.y * 128;
    const int blockCol = blockIdx.x * 128;

    // cp.async thread mapping: A tile 128x32 (2 thr/row, 4 float4 each);
    //                          B tile 32x128 (8 thr/row, 4 float4 each)
    const int arow = tid >> 1;
    const int acol = (tid & 1) * 16;
    const int brow = tid >> 3;
    const int bcol = (tid & 7) * 16;

    int aSrcRow = blockRow + arow;
    if (aSrcRow >= M) aSrcRow = M - 1;   // clamp (results discarded in epilogue)
    const float* Apt = A + (size_t)aSrcRow * K + acol;
    const float* Bpt = B + (size_t)brow * N + blockCol + bcol;

    float acc[8][8];
#pragma unroll
    for (int i = 0; i < 8; i++)
#pragma unroll
        for (int j = 0; j < 8; j++) acc[i][j] = 0.f;

    GEMM_LOADSTAGE_(0, 0);
    CP_WAIT0();
    __syncthreads();

    int s = 0;
    for (int k0 = BK_; k0 < K; k0 += BK_) {
        GEMM_LOADSTAGE_(s ^ 1, k0);
        {
            const float* as = As0 + s * ASTAGE_;
            const float* bs = Bs0 + s * BSTAGE_;
            GEMM_COMPUTE_(as, bs);
        }
        CP_WAIT0();
        __syncthreads();
        s ^= 1;
    }
    {
        const float* as = As0 + s * ASTAGE_;
        const float* bs = Bs0 + s * BSTAGE_;
        GEMM_COMPUTE_(as, bs);
    }

    // ---- epilogue: bias (+gelu), vectorized stores ----
#pragma unroll
    for (int i = 0; i < 8; i++) {
        const int r = blockRow + ty * 8 + i;
        if (r >= M) continue;
        float vals[8];
#pragma unroll
        for (int j = 0; j < 8; j++) {
            const int c = blockCol + tx * 8 + j;
            float val = acc[i][j] + bias[c];
            if (act == 1) {
                float u = 0.7978845608028654f * (val + 0.044715f * val * val * val);
                float t = 1.f - 2.f / (__expf(2.f * u) + 1.f);
                val = 0.5f * val * (1.f + t);
            }
            vals[j] = val;
        }
        *reinterpret_cast<float4*>(C + (size_t)r * N + blockCol + tx * 8) =
            *reinterpret_cast<const float4*>(vals);
        *reinterpret_cast<float4*>(C + (size_t)r * N + blockCol + tx * 8 + 4) =
            *reinterpret_cast<const float4*>(vals + 4);
    }
}

// ---------------- embedding + layernorm ----------------
__global__ __launch_bounds__(256) void embed_ln_kernel(
    const int* __restrict__ x, const int* __restrict__ segs,
    const float* __restrict__ we, const float* __restrict__ pe, const float* __restrict__ te,
    const float* __restrict__ lns, const float* __restrict__ lnb,
    float* __restrict__ hout)
{
    int s = blockIdx.x;
    int tid = threadIdx.x;
    __shared__ float buf[D_];
    __shared__ float red[256];
    int tok = x[s], seg = segs[s];
    float lsum = 0.f;
    for (int d = tid; d < D_; d += 256) {
        float v = we[(size_t)tok * D_ + d] + pe[(size_t)s * D_ + d] + te[(size_t)seg * D_ + d];
        buf[d] = v;
        lsum += v;
    }
    red[tid] = lsum; __syncthreads();
    for (int o = 128; o > 0; o >>= 1) { if (tid < o) red[tid] += red[tid + o]; __syncthreads(); }
    float mean = red[0] / D_;
    __syncthreads();
    float vsum = 0.f;
    for (int d = tid; d < D_; d += 256) { float t = buf[d] - mean; vsum += t * t; }
    red[tid] = vsum; __syncthreads();
    for (int o = 128; o > 0; o >>= 1) { if (tid < o) red[tid] += red[tid + o]; __syncthreads(); }
    float rstd = rsqrtf(red[0] / D_ + 1e-5f);
    for (int d = tid; d < D_; d += 256)
        hout[(size_t)s * D_ + d] = (buf[d] - mean) * rstd * lns[d] + lnb[d];
}

// ---------------- residual add + layernorm (in-place into h) ----------------
__global__ __launch_bounds__(256) void add_ln_kernel(
    float* __restrict__ h, const float* __restrict__ t,
    const float* __restrict__ lns, const float* __restrict__ lnb)
{
    int s = blockIdx.x;
    int tid = threadIdx.x;
    __shared__ float buf[D_];
    __shared__ float red[256];
    float lsum = 0.f;
    for (int d = tid; d < D_; d += 256) {
        float v = h[(size_t)s * D_ + d] + t[(size_t)s * D_ + d];
        buf[d] = v;
        lsum += v;
    }
    red[tid] = lsum; __syncthreads();
    for (int o = 128; o > 0; o >>= 1) { if (tid < o) red[tid] += red[tid + o]; __syncthreads(); }
    float mean = red[0] / D_;
    __syncthreads();
    float vsum = 0.f;
    for (int d = tid; d < D_; d += 256) { float x = buf[d] - mean; vsum += x * x; }
    red[tid] = vsum; __syncthreads();
    for (int o = 128; o > 0; o >>= 1) { if (tid < o) red[tid] += red[tid + o]; __syncthreads(); }
    float rstd = rsqrtf(red[0] / D_ + 1e-5f);
    for (int d = tid; d < D_; d += 256)
        h[(size_t)s * D_ + d] = (buf[d] - mean) * rstd * lns[d] + lnb[d];
}

// ---------------- global flags ----------------
__global__ void zero_flags_kernel(int* f)
{
    int i = blockIdx.x * 256 + threadIdx.x;
    if (i < S_) f[i] = 0;
}
__global__ void set_flags_kernel(const int* __restrict__ clss, int* f)
{
    if (threadIdx.x < NCLS_) f[clss[threadIdx.x]] = 1;
}
__global__ __launch_bounds__(256) void gather_rows_kernel(
    const float* __restrict__ h, const int* __restrict__ clss, float* __restrict__ hg)
{
    int c = blockIdx.x;
    int gp = clss[c];
    for (int d = threadIdx.x; d < D_; d += 256)
        hg[(size_t)c * D_ + d] = h[(size_t)gp * D_ + d];
}

// ================ tiled flash-style band + global-key attention ================
// One block per (64-query chunk, head). 640 keys = 64 global + 576 window,
// in 10 chunks of 64 keys -> smem 68.8KB -> 2 blocks/SM.
#define BKEY_ 64
#define NCH_  10
#define KS_   68
#define VS_   68
#define PS_   72
#define OF_Q  0
#define OF_K  4096                    /* 64*64 Q */
#define OF_V  (OF_K + 64*KS_)         /* 8448 */
#define OF_P  (OF_V + BKEY_*VS_)      /* 12800 */
#define OF_KV (OF_P + BKEY_*PS_)      /* 17408 */
#define OF_SC (OF_KV + BKEY_)         /* 17472 */
#define OF_SI (OF_SC + 64)            /* 17536 */
#define BAND_SMEM ((OF_SI + 64) * 4)  /* 70400 bytes */

__global__ __launch_bounds__(256) void band_attn_tiled_kernel(
    const float* __restrict__ q, const float* __restrict__ k, const float* __restrict__ v,
    const int* __restrict__ clss, const int* __restrict__ mask_src, const int* __restrict__ glb,
    float* __restrict__ out)
{
    extern __shared__ float sm[];
    float* Qsd = sm + OF_Q;          // [d][r]  stride 64
    float* Ksd = sm + OF_K;          // [d][kk] stride KS_
    float* Vs  = sm + OF_V;          // [kk][d] stride VS_
    float* Pkq = sm + OF_P;          // [kk][r] stride PS_
    int*   kvl = (int*)(sm + OF_KV);
    float* ssc = sm + OF_SC;
    float* sin_ = sm + OF_SI;

    const int c = blockIdx.x, hh = blockIdx.y;
    const int s0 = c * 64;
    const int t = threadIdx.x;
    const int w = t >> 5, lane = t & 31;

    for (int idx = t; idx < 64 * 16; idx += 256) {
        const int r = idx >> 4, seg = (idx & 15) * 4;
        const float4 qv = *reinterpret_cast<const float4*>(
            q + ((size_t)(s0 + r) * H_ + hh) * HD_ + seg);
        Qsd[(seg + 0) * 64 + r] = qv.x * 0.125f;
        Qsd[(seg + 1) * 64 + r] = qv.y * 0.125f;
        Qsd[(seg + 2) * 64 + r] = qv.z * 0.125f;
        Qsd[(seg + 3) * 64 + r] = qv.w * 0.125f;
    }

    float mstate = -1e30f, ssum = 0.f;   // live in threads t<64
    float O[8][2];
#pragma unroll
    for (int j = 0; j < 8; j++) { O[j][0] = 0.f; O[j][1] = 0.f; }

    const int tq = t >> 3, tk = t & 7;   // 32 q-groups x 8 k-groups
    const int r0 = tq * 2, kk0 = tk * 8;

    for (int ch = 0; ch < NCH_; ch++) {
        // ---- load K (transposed), V, validity : 64 keys ----
        for (int idx = t; idx < BKEY_ * 16; idx += 256) {
            const int kr = idx >> 4, seg = (idx & 15) * 4;
            const int gi = ch * BKEY_ + kr;
            int p; int val;
            if (gi < NCLS_) {
                p = clss[gi];
                val = (mask_src[p] > 0);
            } else {
                p = s0 + gi - 320;
                val = (p >= 0 && p < S_);
                if (val) val = (mask_src[p] > 0) && (glb[p] == 0);
                if (!val) p = 0;
            }
            if ((idx & 15) == 0) kvl[kr] = val;
            const float4 kv = *reinterpret_cast<const float4*>(
                k + ((size_t)p * H_ + hh) * HD_ + seg);
            Ksd[(seg + 0) * KS_ + kr] = kv.x;
            Ksd[(seg + 1) * KS_ + kr] = kv.y;
            Ksd[(seg + 2) * KS_ + kr] = kv.z;
            Ksd[(seg + 3) * KS_ + kr] = kv.w;
            *reinterpret_cast<float4*>(Vs + kr * VS_ + seg) =
                *reinterpret_cast<const float4*>(v + ((size_t)p * H_ + hh) * HD_ + seg);
        }
        __syncthreads();

        // ---- QK scores: thread computes 2q x 8k ----
        float sc[2][8];
#pragma unroll
        for (int j = 0; j < 2; j++)
#pragma unroll
            for (int i = 0; i < 8; i++) sc[j][i] = 0.f;
#pragma unroll 8
        for (int d = 0; d < 64; d++) {
            const float2 a = *reinterpret_cast<const float2*>(Qsd + d * 64 + r0);
            const float4 b0 = *reinterpret_cast<const float4*>(Ksd + d * KS_ + kk0);
            const float4 b1 = *reinterpret_cast<const float4*>(Ksd + d * KS_ + kk0 + 4);
            const float aa[2] = {a.x, a.y};
            const float bb[8] = {b0.x, b0.y, b0.z, b0.w, b1.x, b1.y, b1.z, b1.w};
#pragma unroll
            for (int j = 0; j < 2; j++)
#pragma unroll
                for (int i = 0; i < 8; i++) sc[j][i] = fmaf(aa[j], bb[i], sc[j][i]);
        }
#pragma unroll
        for (int i = 0; i < 8; i++) {
            const int gi = ch * BKEY_ + kk0 + i;
            const int kvalid = kvl[kk0 + i];
#pragma unroll
            for (int j = 0; j < 2; j++) {
                const int r = r0 + j;
                const bool ok = kvalid &&
                    (gi < NCLS_ || (r >= gi - 576 && r <= gi - 64));
                Pkq[(kk0 + i) * PS_ + r] = ok ? sc[j][i] : -1e30f;
            }
        }
        __syncthreads();

        // ---- online softmax update (threads < 64, one per query) ----
        if (t < 64) {
            float mn = mstate;
            for (int kk = 0; kk < BKEY_; kk++) mn = fmaxf(mn, Pkq[kk * PS_ + t]);
            const float scale = (mn <= -1e29f) ? 1.f : __expf(mstate - mn);
            float ls = 0.f;
            for (int kk = 0; kk < BKEY_; kk++) {
                const float sv = Pkq[kk * PS_ + t];
                const float pv = (sv <= -1e29f) ? 0.f : __expf(sv - mn);
                Pkq[kk * PS_ + t] = pv;
                ls += pv;
            }
            ssum = ssum * scale + ls;
            mstate = mn;
            ssc[t] = scale;
        }
        __syncthreads();

        // ---- PV accumulate: warp handles queries w*8..w*8+7, lane dims {lane, lane+32} ----
        {
#pragma unroll
            for (int j = 0; j < 8; j++) {
                const float scj = ssc[w * 8 + j];
                O[j][0] *= scj; O[j][1] *= scj;
            }
            for (int kk = 0; kk < BKEY_; kk++) {
                const float4 pa = *reinterpret_cast<const float4*>(Pkq + kk * PS_ + w * 8);
                const float4 pb = *reinterpret_cast<const float4*>(Pkq + kk * PS_ + w * 8 + 4);
                const float v0 = Vs[kk * VS_ + lane];
                const float v1 = Vs[kk * VS_ + lane + 32];
                O[0][0] = fmaf(pa.x, v0, O[0][0]); O[0][1] = fmaf(pa.x, v1, O[0][1]);
                O[1][0] = fmaf(pa.y, v0, O[1][0]); O[1][1] = fmaf(pa.y, v1, O[1][1]);
                O[2][0] = fmaf(pa.z, v0, O[2][0]); O[2][1] = fmaf(pa.z, v1, O[2][1]);
                O[3][0] = fmaf(pa.w, v0, O[3][0]); O[3][1] = fmaf(pa.w, v1, O[3][1]);
                O[4][0] = fmaf(pb.x, v0, O[4][0]); O[4][1] = fmaf(pb.x, v1, O[4][1]);
                O[5][0] = fmaf(pb.y, v0, O[5][0]); O[5][1] = fmaf(pb.y, v1, O[5][1]);
                O[6][0] = fmaf(pb.z, v0, O[6][0]); O[6][1] = fmaf(pb.z, v1, O[6][1]);
                O[7][0] = fmaf(pb.w, v0, O[7][0]); O[7][1] = fmaf(pb.w, v1, O[7][1]);
            }
        }
        __syncthreads();
    }

    if (t < 64) sin_[t] = 1.f / ssum;
    __syncthreads();
#pragma unroll
    for (int j = 0; j < 8; j++) {
        const int qr = w * 8 + j;
        const float inv = sin_[qr];
        float* op = out + ((size_t)(s0 + qr) * H_ + hh) * HD_;
        op[lane]      = O[j][0] * inv;
        op[lane + 32] = O[j][1] * inv;
    }
}

// ---------------- global-query full attention: one block per (c, head) ----------------
__global__ __launch_bounds__(256) void glb_attn_kernel(
    const float* __restrict__ qg, const float* __restrict__ kg, const float* __restrict__ vg,
    const int* __restrict__ clss, const int* __restrict__ mask_src,
    float* __restrict__ out)
{
    const int c = blockIdx.x;
    const int h = blockIdx.y;
    __shared__ float qs[HD_];
    __shared__ float sc[S_];
    __shared__ float red[256];
    const int tid = threadIdx.x;
    const int lane = tid & 31;
    const int w = tid >> 5;

    if (tid < HD_) qs[tid] = qg[((size_t)c * H_ + h) * HD_ + tid] * 0.125f;
    __syncthreads();

    for (int p = w; p < S_; p += 8) {
        const float* kp = kg + ((size_t)p * H_ + h) * HD_;
        float sdot = qs[lane] * kp[lane] + qs[lane + 32] * kp[lane + 32];
#pragma unroll
        for (int o = 16; o > 0; o >>= 1) sdot += __shfl_xor_sync(0xffffffffu, sdot, o);
        if (lane == 0) sc[p] = (mask_src[p] > 0) ? sdot : -1e30f;
    }
    __syncthreads();

    float m = -1e30f;
    for (int p = tid; p < S_; p += 256) m = fmaxf(m, sc[p]);
    red[tid] = m; __syncthreads();
    for (int o = 128; o > 0; o >>= 1) { if (tid < o) red[tid] = fmaxf(red[tid], red[tid + o]); __syncthreads(); }
    m = red[0];
    __syncthreads();
    float sum = 0.f;
    for (int p = tid; p < S_; p += 256) { float e = __expf(sc[p] - m); sc[p] = e; sum += e; }
    red[tid] = sum; __syncthreads();
    for (int o = 128; o > 0; o >>= 1) { if (tid < o) red[tid] += red[tid + o]; __syncthreads(); }
    float inv = 1.f / red[0];
    __syncthreads();

    int d = tid & 63, quarter = tid >> 6;
    float acc = 0.f;
    for (int p = quarter; p < S_; p += 4)
        acc += sc[p] * vg[((size_t)p * H_ + h) * HD_ + d];
    red[tid] = acc; __syncthreads();
    if (tid < 64) {
        float o = (red[tid] + red[tid + 64] + red[tid + 128] + red[tid + 192]) * inv;
        int gp = clss[c];
        out[((size_t)gp * H_ + h) * HD_ + tid] = o;
    }
}

// ---------------- driver ----------------
static void run_gemm(const float* A, const float* B, const float* bias, float* C,
                     int M, int N, int K, int act)
{
    dim3 grid(N / 128, (M + 127) / 128);
    sgemm_kernel<<<grid, 256, GEMM_SMEM>>>(A, B, bias, C, M, N, K, act);
}

extern "C" void kernel_launch(void* const* d_in, const int* in_sizes, int n_in,
                              void* d_out, int out_size)
{
    (void)in_sizes; (void)n_in;
    const int*   x        = (const int*)d_in[0];
    const int*   mask_src = (const int*)d_in[1];
    const int*   clss     = (const int*)d_in[2];
    const int*   segs     = (const int*)d_in[3];
    const float* word_emb = (const float*)d_in[4];
    const float* pos_emb  = (const float*)d_in[5];
    const float* type_emb = (const float*)d_in[6];
    const float* ln_e_s   = (const float*)d_in[7];
    const float* ln_e_b   = (const float*)d_in[8];
    const float* Wq  = (const float*)d_in[9];   const float* bq  = (const float*)d_in[10];
    const float* Wk  = (const float*)d_in[11];  const float* bk  = (const float*)d_in[12];
    const float* Wv  = (const float*)d_in[13];  const float* bv  = (const float*)d_in[14];
    const float* Wqg = (const float*)d_in[15];  const float* bqg = (const float*)d_in[16];
    const float* Wkg = (const float*)d_in[17];  const float* bkg = (const float*)d_in[18];
    const float* Wvg = (const float*)d_in[19];  const float* bvg = (const float*)d_in[20];
    const float* Wo  = (const float*)d_in[21];  const float* bo  = (const float*)d_in[22];
    const float* ln1_s = (const float*)d_in[23]; const float* ln1_b = (const float*)d_in[24];
    const float* Wf1 = (const float*)d_in[25];  const float* bf1 = (const float*)d_in[26];
    const float* Wf2 = (const float*)d_in[27];  const float* bf2 = (const float*)d_in[28];
    const float* ln2_s = (const float*)d_in[29]; const float* ln2_b = (const float*)d_in[30];

    float *h, *q, *k, *v, *kg, *vg, *outb, *tmp, *ff, *hg, *qg;
    int* glb;
    cudaGetSymbolAddress((void**)&h,    g_h);
    cudaGetSymbolAddress((void**)&q,    g_q);
    cudaGetSymbolAddress((void**)&k,    g_k);
    cudaGetSymbolAddress((void**)&v,    g_v);
    cudaGetSymbolAddress((void**)&kg,   g_kg);
    cudaGetSymbolAddress((void**)&vg,   g_vg);
    cudaGetSymbolAddress((void**)&outb, g_out);
    cudaGetSymbolAddress((void**)&tmp,  g_tmp);
    cudaGetSymbolAddress((void**)&ff,   g_ff);
    cudaGetSymbolAddress((void**)&hg,   g_hg);
    cudaGetSymbolAddress((void**)&qg,   g_qg);
    cudaGetSymbolAddress((void**)&glb,  g_glb);

    cudaFuncSetAttribute(band_attn_tiled_kernel,
                         cudaFuncAttributeMaxDynamicSharedMemorySize, BAND_SMEM);
    cudaFuncSetAttribute(sgemm_kernel,
                         cudaFuncAttributeMaxDynamicSharedMemorySize, GEMM_SMEM);

    // embedding + LN
    embed_ln_kernel<<<S_, 256>>>(x, segs, word_emb, pos_emb, type_emb, ln_e_s, ln_e_b, h);

    // global flags
    zero_flags_kernel<<<(S_ + 255) / 256, 256>>>(glb);
    set_flags_kernel<<<1, 64>>>(clss, glb);

    const size_t DD = (size_t)D_ * D_;
    for (int l = 0; l < LAYERS_; l++) {
        // Q K V projections
        run_gemm(h, Wq + l * DD, bq + l * D_, q, S_, D_, D_, 0);
        run_gemm(h, Wk + l * DD, bk + l * D_, k, S_, D_, D_, 0);
        run_gemm(h, Wv + l * DD, bv + l * D_, v, S_, D_, D_, 0);

        // tiled band + global-key attention (writes all rows of outb)
        band_attn_tiled_kernel<<<dim3(S_ / 64, H_), 256, BAND_SMEM>>>(
            q, k, v, clss, mask_src, glb, outb);

        // global-query path
        gather_rows_kernel<<<NCLS_, 256>>>(h, clss, hg);
        run_gemm(hg, Wqg + l * DD, bqg + l * D_, qg, NCLS_, D_, D_, 0);
        run_gemm(h, Wkg + l * DD, bkg + l * D_, kg, S_, D_, D_, 0);
        run_gemm(h, Wvg + l * DD, bvg + l * D_, vg, S_, D_, D_, 0);
        glb_attn_kernel<<<dim3(NCLS_, H_), 256>>>(qg, kg, vg, clss, mask_src, outb);

        // output projection + residual LN
        run_gemm(outb, Wo + l * DD, bo + l * D_, tmp, S_, D_, D_, 0);
        add_ln_kernel<<<S_, 256>>>(h, tmp, ln1_s + l * D_, ln1_b + l * D_);

        // feed-forward
        run_gemm(h,  Wf1 + (size_t)l * D_ * FF_, bf1 + l * FF_, ff,  S_, FF_, D_, 1);
        run_gemm(ff, Wf2 + (size_t)l * D_ * FF_, bf2 + l * D_,  tmp, S_, D_, FF_, 0);
        add_ln_kernel<<<S_, 256>>>(h, tmp, ln2_s + l * D_, ln2_b + l * D_);
    }

    cudaMemcpyAsync(d_out, h, (size_t)out_size * sizeof(float), cudaMemcpyDeviceToDevice);
}

// round 14
// speedup vs baseline: 1.1279x; 1.1279x over previous
#include <cuda_runtime.h>
#include <math.h>
#include <stdint.h>

#define S_    4096
#define D_    768
#define H_    12
#define HD_   64
#define NCLS_ 64
#define FF_   3072
#define WIN_  256
#define LAYERS_ 2

// ---------------- scratch (static device globals; no allocation) ----------------
__device__ float g_h  [S_*D_];
__device__ float g_q  [S_*D_];
__device__ float g_k  [S_*D_];
__device__ float g_v  [S_*D_];
__device__ float g_kg [S_*D_];
__device__ float g_vg [S_*D_];
__device__ float g_out[S_*D_];
__device__ float g_tmp[S_*D_];
__device__ float g_ff [S_*FF_];
__device__ float g_hg [NCLS_*D_];
__device__ float g_qg [NCLS_*D_];
__device__ int   g_glb[S_];

// ---------------- fp32 SGEMM: C = A(MxK) @ B(KxN) + bias, optional gelu ----------------
// 64x128 tile, 128 threads, BK=16, double-buffered smem + gmem register prefetch +
// register fragment double-buffering. 4 blocks/SM.
#define BK_   16
#define SAS_  68    /* padded A-tile k-row stride (floats): 64 rows + 4 pad */

#define LOADFRAG_(af, bf, as, bs, kk)                                                        \
    *reinterpret_cast<float4*>(af)       = *reinterpret_cast<const float4*>((as) + (kk) * SAS_ + ty * 8);     \
    *reinterpret_cast<float4*>((af) + 4) = *reinterpret_cast<const float4*>((as) + (kk) * SAS_ + ty * 8 + 4); \
    *reinterpret_cast<float4*>(bf)       = *reinterpret_cast<const float4*>((bs) + (kk) * 128 + tx * 8);      \
    *reinterpret_cast<float4*>((bf) + 4) = *reinterpret_cast<const float4*>((bs) + (kk) * 128 + tx * 8 + 4);

#define FMA88_(af, bf)                                       \
    _Pragma("unroll")                                        \
    for (int i_ = 0; i_ < 8; i_++)                           \
        _Pragma("unroll")                                    \
        for (int j_ = 0; j_ < 8; j_++)                       \
            acc[i_][j_] = fmaf((af)[i_], (bf)[j_], acc[i_][j_]);

__global__ __launch_bounds__(128, 4) void sgemm_kernel(
    const float* __restrict__ A, const float* __restrict__ B,
    const float* __restrict__ bias, float* __restrict__ C,
    int M, int N, int K, int act)
{
    __shared__ float As[2][BK_ * SAS_];
    __shared__ float Bs[2][BK_ * 128];
    const int tid = threadIdx.x;
    const int tx = tid & 15;          // 16 threads along N (8 cols each)
    const int ty = tid >> 4;          // 8 threads along M (8 rows each)
    const int blockRow = blockIdx.y * 64;
    const int blockCol = blockIdx.x * 128;
    // A tile 64x16: each thread loads 8 floats of one row (2 thr/row)
    const int aRow = tid >> 1;
    const int aCol = (tid & 1) * 8;
    // B tile 16x128: each thread loads 16 floats of one k-row (8 thr/row)
    const int bRow = tid >> 3;
    const int bCol = (tid & 7) * 16;

    float acc[8][8];
#pragma unroll
    for (int i = 0; i < 8; i++)
#pragma unroll
        for (int j = 0; j < 8; j++) acc[i][j] = 0.f;

    const float* Ap = A + (size_t)(blockRow + aRow) * K + aCol;
    const float* Bp = B + (size_t)bRow * N + blockCol + bCol;
    const bool aOk = (blockRow + aRow) < M;

    float4 pa0, pa1, pb[4];
    // ---- preload tile 0 ----
    pa0 = make_float4(0.f, 0.f, 0.f, 0.f); pa1 = pa0;
    if (aOk) { pa0 = *reinterpret_cast<const float4*>(Ap);
               pa1 = *reinterpret_cast<const float4*>(Ap + 4); }
#pragma unroll
    for (int c = 0; c < 4; c++)
        pb[c] = *reinterpret_cast<const float4*>(Bp + c * 4);
    {
        float* as = As[0];
        as[(aCol + 0) * SAS_ + aRow] = pa0.x;
        as[(aCol + 1) * SAS_ + aRow] = pa0.y;
        as[(aCol + 2) * SAS_ + aRow] = pa0.z;
        as[(aCol + 3) * SAS_ + aRow] = pa0.w;
        as[(aCol + 4) * SAS_ + aRow] = pa1.x;
        as[(aCol + 5) * SAS_ + aRow] = pa1.y;
        as[(aCol + 6) * SAS_ + aRow] = pa1.z;
        as[(aCol + 7) * SAS_ + aRow] = pa1.w;
#pragma unroll
        for (int c = 0; c < 4; c++)
            *reinterpret_cast<float4*>(Bs[0] + bRow * 128 + bCol + c * 4) = pb[c];
    }
    __syncthreads();

    int s = 0;
    for (int k0 = BK_; k0 < K; k0 += BK_) {
        // prefetch next gmem tile into registers
        pa0 = make_float4(0.f, 0.f, 0.f, 0.f); pa1 = pa0;
        if (aOk) { pa0 = *reinterpret_cast<const float4*>(Ap + k0);
                   pa1 = *reinterpret_cast<const float4*>(Ap + k0 + 4); }
#pragma unroll
        for (int c = 0; c < 4; c++)
            pb[c] = *reinterpret_cast<const float4*>(Bp + (size_t)k0 * N + c * 4);

        // compute current tile with fragment double-buffering
        {
            const float* as = As[s];
            const float* bs = Bs[s];
            float af[2][8], bf[2][8];
            LOADFRAG_(af[0], bf[0], as, bs, 0);
#pragma unroll
            for (int kk = 0; kk < BK_; kk++) {
                const int cur = kk & 1;
                if (kk + 1 < BK_) {
                    LOADFRAG_(af[cur ^ 1], bf[cur ^ 1], as, bs, kk + 1);
                }
                FMA88_(af[cur], bf[cur]);
            }
        }

        // store prefetched tile into the other buffer
        float* asn = As[s ^ 1];
        asn[(aCol + 0) * SAS_ + aRow] = pa0.x;
        asn[(aCol + 1) * SAS_ + aRow] = pa0.y;
        asn[(aCol + 2) * SAS_ + aRow] = pa0.z;
        asn[(aCol + 3) * SAS_ + aRow] = pa0.w;
        asn[(aCol + 4) * SAS_ + aRow] = pa1.x;
        asn[(aCol + 5) * SAS_ + aRow] = pa1.y;
        asn[(aCol + 6) * SAS_ + aRow] = pa1.z;
        asn[(aCol + 7) * SAS_ + aRow] = pa1.w;
#pragma unroll
        for (int c = 0; c < 4; c++)
            *reinterpret_cast<float4*>(Bs[s ^ 1] + bRow * 128 + bCol + c * 4) = pb[c];
        __syncthreads();
        s ^= 1;
    }

    // last tile
    {
        const float* as = As[s];
        const float* bs = Bs[s];
        float af[2][8], bf[2][8];
        LOADFRAG_(af[0], bf[0], as, bs, 0);
#pragma unroll
        for (int kk = 0; kk < BK_; kk++) {
            const int cur = kk & 1;
            if (kk + 1 < BK_) {
                LOADFRAG_(af[cur ^ 1], bf[cur ^ 1], as, bs, kk + 1);
            }
            FMA88_(af[cur], bf[cur]);
        }
    }

#pragma unroll
    for (int i = 0; i < 8; i++) {
        int r = blockRow + ty * 8 + i;
        if (r >= M) continue;
        float vals[8];
#pragma unroll
        for (int j = 0; j < 8; j++) {
            int c = blockCol + tx * 8 + j;
            float val = acc[i][j] + bias[c];
            if (act == 1) {
                float u = 0.7978845608028654f * (val + 0.044715f * val * val * val);
                float t = 1.f - 2.f / (__expf(2.f * u) + 1.f);
                val = 0.5f * val * (1.f + t);
            }
            vals[j] = val;
        }
        *reinterpret_cast<float4*>(C + (size_t)r * N + blockCol + tx * 8) =
            *reinterpret_cast<const float4*>(vals);
        *reinterpret_cast<float4*>(C + (size_t)r * N + blockCol + tx * 8 + 4) =
            *reinterpret_cast<const float4*>(vals + 4);
    }
}

// ---------------- embedding + layernorm ----------------
__global__ __launch_bounds__(256) void embed_ln_kernel(
    const int* __restrict__ x, const int* __restrict__ segs,
    const float* __restrict__ we, const float* __restrict__ pe, const float* __restrict__ te,
    const float* __restrict__ lns, const float* __restrict__ lnb,
    float* __restrict__ hout)
{
    int s = blockIdx.x;
    int tid = threadIdx.x;
    __shared__ float buf[D_];
    __shared__ float red[256];
    int tok = x[s], seg = segs[s];
    float lsum = 0.f;
    for (int d = tid; d < D_; d += 256) {
        float v = we[(size_t)tok * D_ + d] + pe[(size_t)s * D_ + d] + te[(size_t)seg * D_ + d];
        buf[d] = v;
        lsum += v;
    }
    red[tid] = lsum; __syncthreads();
    for (int o = 128; o > 0; o >>= 1) { if (tid < o) red[tid] += red[tid + o]; __syncthreads(); }
    float mean = red[0] / D_;
    __syncthreads();
    float vsum = 0.f;
    for (int d = tid; d < D_; d += 256) { float t = buf[d] - mean; vsum += t * t; }
    red[tid] = vsum; __syncthreads();
    for (int o = 128; o > 0; o >>= 1) { if (tid < o) red[tid] += red[tid + o]; __syncthreads(); }
    float rstd = rsqrtf(red[0] / D_ + 1e-5f);
    for (int d = tid; d < D_; d += 256)
        hout[(size_t)s * D_ + d] = (buf[d] - mean) * rstd * lns[d] + lnb[d];
}

// ---------------- residual add + layernorm (in-place into h) ----------------
__global__ __launch_bounds__(256) void add_ln_kernel(
    float* __restrict__ h, const float* __restrict__ t,
    const float* __restrict__ lns, const float* __restrict__ lnb)
{
    int s = blockIdx.x;
    int tid = threadIdx.x;
    __shared__ float buf[D_];
    __shared__ float red[256];
    float lsum = 0.f;
    for (int d = tid; d < D_; d += 256) {
        float v = h[(size_t)s * D_ + d] + t[(size_t)s * D_ + d];
        buf[d] = v;
        lsum += v;
    }
    red[tid] = lsum; __syncthreads();
    for (int o = 128; o > 0; o >>= 1) { if (tid < o) red[tid] += red[tid + o]; __syncthreads(); }
    float mean = red[0] / D_;
    __syncthreads();
    float vsum = 0.f;
    for (int d = tid; d < D_; d += 256) { float x = buf[d] - mean; vsum += x * x; }
    red[tid] = vsum; __syncthreads();
    for (int o = 128; o > 0; o >>= 1) { if (tid < o) red[tid] += red[tid + o]; __syncthreads(); }
    float rstd = rsqrtf(red[0] / D_ + 1e-5f);
    for (int d = tid; d < D_; d += 256)
        h[(size_t)s * D_ + d] = (buf[d] - mean) * rstd * lns[d] + lnb[d];
}

// ---------------- global flags ----------------
__global__ void zero_flags_kernel(int* f)
{
    int i = blockIdx.x * 256 + threadIdx.x;
    if (i < S_) f[i] = 0;
}
__global__ void set_flags_kernel(const int* __restrict__ clss, int* f)
{
    if (threadIdx.x < NCLS_) f[clss[threadIdx.x]] = 1;
}
__global__ __launch_bounds__(256) void gather_rows_kernel(
    const float* __restrict__ h, const int* __restrict__ clss, float* __restrict__ hg)
{
    int c = blockIdx.x;
    int gp = clss[c];
    for (int d = threadIdx.x; d < D_; d += 256)
        hg[(size_t)c * D_ + d] = h[(size_t)gp * D_ + d];
}

// ================ tiled flash-style band + global-key attention ================
#define BKEY_ 128
#define NCH_  5
#define KS_   132
#define VS_   68
#define PS_   72
#define OF_Q  0
#define OF_K  4096
#define OF_V  (OF_K + 64*KS_)
#define OF_P  (OF_V + BKEY_*VS_)
#define OF_KV (OF_P + BKEY_*PS_)
#define OF_SC (OF_KV + BKEY_)
#define OF_SI (OF_SC + 64)
#define BAND_SMEM ((OF_SI + 64) * 4)

__global__ __launch_bounds__(256) void band_attn_tiled_kernel(
    const float* __restrict__ q, const float* __restrict__ k, const float* __restrict__ v,
    const int* __restrict__ clss, const int* __restrict__ mask_src, const int* __restrict__ glb,
    float* __restrict__ out)
{
    extern __shared__ float sm[];
    float* Qsd = sm + OF_Q;
    float* Ksd = sm + OF_K;
    float* Vs  = sm + OF_V;
    float* Pkq = sm + OF_P;
    int*   kvl = (int*)(sm + OF_KV);
    float* ssc = sm + OF_SC;
    float* sin_ = sm + OF_SI;

    const int c = blockIdx.x, hh = blockIdx.y;
    const int s0 = c * 64;
    const int t = threadIdx.x;
    const int w = t >> 5, lane = t & 31;

    for (int idx = t; idx < 64 * 16; idx += 256) {
        const int r = idx >> 4, seg = (idx & 15) * 4;
        const float4 qv = *reinterpret_cast<const float4*>(
            q + ((size_t)(s0 + r) * H_ + hh) * HD_ + seg);
        Qsd[(seg + 0) * 64 + r] = qv.x * 0.125f;
        Qsd[(seg + 1) * 64 + r] = qv.y * 0.125f;
        Qsd[(seg + 2) * 64 + r] = qv.z * 0.125f;
        Qsd[(seg + 3) * 64 + r] = qv.w * 0.125f;
    }

    float mstate = -1e30f, ssum = 0.f;
    float O[8][2];
#pragma unroll
    for (int j = 0; j < 8; j++) { O[j][0] = 0.f; O[j][1] = 0.f; }

    const int tq = t >> 4, tk = t & 15;
    const int r0 = tq * 4, kk0 = tk * 8;

    for (int ch = 0; ch < NCH_; ch++) {
        for (int idx = t; idx < BKEY_ * 16; idx += 256) {
            const int kr = idx >> 4, seg = (idx & 15) * 4;
            const int gi = ch * BKEY_ + kr;
            int p; int val;
            if (gi < NCLS_) {
                p = clss[gi];
                val = (mask_src[p] > 0);
            } else {
                p = s0 + gi - 320;
                val = (p >= 0 && p < S_);
                if (val) val = (mask_src[p] > 0) && (glb[p] == 0);
                if (!val) p = 0;
            }
            if ((idx & 15) == 0) kvl[kr] = val;
            const float4 kv = *reinterpret_cast<const float4*>(
                k + ((size_t)p * H_ + hh) * HD_ + seg);
            Ksd[(seg + 0) * KS_ + kr] = kv.x;
            Ksd[(seg + 1) * KS_ + kr] = kv.y;
            Ksd[(seg + 2) * KS_ + kr] = kv.z;
            Ksd[(seg + 3) * KS_ + kr] = kv.w;
            *reinterpret_cast<float4*>(Vs + kr * VS_ + seg) =
                *reinterpret_cast<const float4*>(v + ((size_t)p * H_ + hh) * HD_ + seg);
        }
        __syncthreads();

        float sc[4][8];
#pragma unroll
        for (int j = 0; j < 4; j++)
#pragma unroll
            for (int i = 0; i < 8; i++) sc[j][i] = 0.f;
#pragma unroll 8
        for (int d = 0; d < 64; d++) {
            const float4 a = *reinterpret_cast<const float4*>(Qsd + d * 64 + r0);
            const float4 b0 = *reinterpret_cast<const float4*>(Ksd + d * KS_ + kk0);
            const float4 b1 = *reinterpret_cast<const float4*>(Ksd + d * KS_ + kk0 + 4);
            const float aa[4] = {a.x, a.y, a.z, a.w};
            const float bb[8] = {b0.x, b0.y, b0.z, b0.w, b1.x, b1.y, b1.z, b1.w};
#pragma unroll
            for (int j = 0; j < 4; j++)
#pragma unroll
                for (int i = 0; i < 8; i++) sc[j][i] = fmaf(aa[j], bb[i], sc[j][i]);
        }
#pragma unroll
        for (int i = 0; i < 8; i++) {
            const int gi = ch * BKEY_ + kk0 + i;
            const int kvalid = kvl[kk0 + i];
#pragma unroll
            for (int j = 0; j < 4; j++) {
                const int r = r0 + j;
                const bool ok = kvalid &&
                    (gi < NCLS_ || (r >= gi - 576 && r <= gi - 64));
                Pkq[(kk0 + i) * PS_ + r] = ok ? sc[j][i] : -1e30f;
            }
        }
        __syncthreads();

        if (t < 64) {
            float mn = mstate;
            for (int kk = 0; kk < BKEY_; kk++) mn = fmaxf(mn, Pkq[kk * PS_ + t]);
            const float scale = (mn <= -1e29f) ? 1.f : __expf(mstate - mn);
            float ls = 0.f;
            for (int kk = 0; kk < BKEY_; kk++) {
                const float sv = Pkq[kk * PS_ + t];
                const float pv = (sv <= -1e29f) ? 0.f : __expf(sv - mn);
                Pkq[kk * PS_ + t] = pv;
                ls += pv;
            }
            ssum = ssum * scale + ls;
            mstate = mn;
            ssc[t] = scale;
        }
        __syncthreads();

        {
#pragma unroll
            for (int j = 0; j < 8; j++) {
                const float scj = ssc[w * 8 + j];
                O[j][0] *= scj; O[j][1] *= scj;
            }
            for (int kk = 0; kk < BKEY_; kk++) {
                const float4 pa = *reinterpret_cast<const float4*>(Pkq + kk * PS_ + w * 8);
                const float4 pb = *reinterpret_cast<const float4*>(Pkq + kk * PS_ + w * 8 + 4);
                const float v0 = Vs[kk * VS_ + lane];
                const float v1 = Vs[kk * VS_ + lane + 32];
                O[0][0] = fmaf(pa.x, v0, O[0][0]); O[0][1] = fmaf(pa.x, v1, O[0][1]);
                O[1][0] = fmaf(pa.y, v0, O[1][0]); O[1][1] = fmaf(pa.y, v1, O[1][1]);
                O[2][0] = fmaf(pa.z, v0, O[2][0]); O[2][1] = fmaf(pa.z, v1, O[2][1]);
                O[3][0] = fmaf(pa.w, v0, O[3][0]); O[3][1] = fmaf(pa.w, v1, O[3][1]);
                O[4][0] = fmaf(pb.x, v0, O[4][0]); O[4][1] = fmaf(pb.x, v1, O[4][1]);
                O[5][0] = fmaf(pb.y, v0, O[5][0]); O[5][1] = fmaf(pb.y, v1, O[5][1]);
                O[6][0] = fmaf(pb.z, v0, O[6][0]); O[6][1] = fmaf(pb.z, v1, O[6][1]);
                O[7][0] = fmaf(pb.w, v0, O[7][0]); O[7][1] = fmaf(pb.w, v1, O[7][1]);
            }
        }
        __syncthreads();
    }

    if (t < 64) sin_[t] = 1.f / ssum;
    __syncthreads();
#pragma unroll
    for (int j = 0; j < 8; j++) {
        const int qr = w * 8 + j;
        const float inv = sin_[qr];
        float* op = out + ((size_t)(s0 + qr) * H_ + hh) * HD_;
        op[lane]      = O[j][0] * inv;
        op[lane + 32] = O[j][1] * inv;
    }
}

// ---------------- global-query full attention: one block per (c, head) ----------------
__global__ __launch_bounds__(256) void glb_attn_kernel(
    const float* __restrict__ qg, const float* __restrict__ kg, const float* __restrict__ vg,
    const int* __restrict__ clss, const int* __restrict__ mask_src,
    float* __restrict__ out)
{
    const int c = blockIdx.x;
    const int h = blockIdx.y;
    __shared__ float qs[HD_];
    __shared__ float sc[S_];
    __shared__ float red[256];
    const int tid = threadIdx.x;
    const int lane = tid & 31;
    const int w = tid >> 5;

    if (tid < HD_) qs[tid] = qg[((size_t)c * H_ + h) * HD_ + tid] * 0.125f;
    __syncthreads();

    for (int p = w; p < S_; p += 8) {
        const float* kp = kg + ((size_t)p * H_ + h) * HD_;
        float sdot = qs[lane] * kp[lane] + qs[lane + 32] * kp[lane + 32];
#pragma unroll
        for (int o = 16; o > 0; o >>= 1) sdot += __shfl_xor_sync(0xffffffffu, sdot, o);
        if (lane == 0) sc[p] = (mask_src[p] > 0) ? sdot : -1e30f;
    }
    __syncthreads();

    float m = -1e30f;
    for (int p = tid; p < S_; p += 256) m = fmaxf(m, sc[p]);
    red[tid] = m; __syncthreads();
    for (int o = 128; o > 0; o >>= 1) { if (tid < o) red[tid] = fmaxf(red[tid], red[tid + o]); __syncthreads(); }
    m = red[0];
    __syncthreads();
    float sum = 0.f;
    for (int p = tid; p < S_; p += 256) { float e = __expf(sc[p] - m); sc[p] = e; sum += e; }
    red[tid] = sum; __syncthreads();
    for (int o = 128; o > 0; o >>= 1) { if (tid < o) red[tid] += red[tid + o]; __syncthreads(); }
    float inv = 1.f / red[0];
    __syncthreads();

    int d = tid & 63, quarter = tid >> 6;
    float acc = 0.f;
    for (int p = quarter; p < S_; p += 4)
        acc += sc[p] * vg[((size_t)p * H_ + h) * HD_ + d];
    red[tid] = acc; __syncthreads();
    if (tid < 64) {
        float o = (red[tid] + red[tid + 64] + red[tid + 128] + red[tid + 192]) * inv;
        int gp = clss[c];
        out[((size_t)gp * H_ + h) * HD_ + tid] = o;
    }
}

// ---------------- driver ----------------
static void run_gemm(const float* A, const float* B, const float* bias, float* C,
                     int M, int N, int K, int act)
{
    dim3 grid(N / 128, (M + 63) / 64);
    sgemm_kernel<<<grid, 128>>>(A, B, bias, C, M, N, K, act);
}

extern "C" void kernel_launch(void* const* d_in, const int* in_sizes, int n_in,
                              void* d_out, int out_size)
{
    (void)in_sizes; (void)n_in;
    const int*   x        = (const int*)d_in[0];
    const int*   mask_src = (const int*)d_in[1];
    const int*   clss     = (const int*)d_in[2];
    const int*   segs     = (const int*)d_in[3];
    const float* word_emb = (const float*)d_in[4];
    const float* pos_emb  = (const float*)d_in[5];
    const float* type_emb = (const float*)d_in[6];
    const float* ln_e_s   = (const float*)d_in[7];
    const float* ln_e_b   = (const float*)d_in[8];
    const float* Wq  = (const float*)d_in[9];   const float* bq  = (const float*)d_in[10];
    const float* Wk  = (const float*)d_in[11];  const float* bk  = (const float*)d_in[12];
    const float* Wv  = (const float*)d_in[13];  const float* bv  = (const float*)d_in[14];
    const float* Wqg = (const float*)d_in[15];  const float* bqg = (const float*)d_in[16];
    const float* Wkg = (const float*)d_in[17];  const float* bkg = (const float*)d_in[18];
    const float* Wvg = (const float*)d_in[19];  const float* bvg = (const float*)d_in[20];
    const float* Wo  = (const float*)d_in[21];  const float* bo  = (const float*)d_in[22];
    const float* ln1_s = (const float*)d_in[23]; const float* ln1_b = (const float*)d_in[24];
    const float* Wf1 = (const float*)d_in[25];  const float* bf1 = (const float*)d_in[26];
    const float* Wf2 = (const float*)d_in[27];  const float* bf2 = (const float*)d_in[28];
    const float* ln2_s = (const float*)d_in[29]; const float* ln2_b = (const float*)d_in[30];

    float *h, *q, *k, *v, *kg, *vg, *outb, *tmp, *ff, *hg, *qg;
    int* glb;
    cudaGetSymbolAddress((void**)&h,    g_h);
    cudaGetSymbolAddress((void**)&q,    g_q);
    cudaGetSymbolAddress((void**)&k,    g_k);
    cudaGetSymbolAddress((void**)&v,    g_v);
    cudaGetSymbolAddress((void**)&kg,   g_kg);
    cudaGetSymbolAddress((void**)&vg,   g_vg);
    cudaGetSymbolAddress((void**)&outb, g_out);
    cudaGetSymbolAddress((void**)&tmp,  g_tmp);
    cudaGetSymbolAddress((void**)&ff,   g_ff);
    cudaGetSymbolAddress((void**)&hg,   g_hg);
    cudaGetSymbolAddress((void**)&qg,   g_qg);
    cudaGetSymbolAddress((void**)&glb,  g_glb);

    cudaFuncSetAttribute(band_attn_tiled_kernel,
                         cudaFuncAttributeMaxDynamicSharedMemorySize, BAND_SMEM);

    // embedding + LN
    embed_ln_kernel<<<S_, 256>>>(x, segs, word_emb, pos_emb, type_emb, ln_e_s, ln_e_b, h);

    // global flags
    zero_flags_kernel<<<(S_ + 255) / 256, 256>>>(glb);
    set_flags_kernel<<<1, 64>>>(clss, glb);

    const size_t DD = (size_t)D_ * D_;
    for (int l = 0; l < LAYERS_; l++) {
        // Q K V projections
        run_gemm(h, Wq + l * DD, bq + l * D_, q, S_, D_, D_, 0);
        run_gemm(h, Wk + l * DD, bk + l * D_, k, S_, D_, D_, 0);
        run_gemm(h, Wv + l * DD, bv + l * D_, v, S_, D_, D_, 0);

        // tiled band + global-key attention (writes all rows of outb)
        band_attn_tiled_kernel<<<dim3(S_ / 64, H_), 256, BAND_SMEM>>>(
            q, k, v, clss, mask_src, glb, outb);

        // global-query path
        gather_rows_kernel<<<NCLS_, 256>>>(h, clss, hg);
        run_gemm(hg, Wqg + l * DD, bqg + l * D_, qg, NCLS_, D_, D_, 0);
        run_gemm(h, Wkg + l * DD, bkg + l * D_, kg, S_, D_, D_, 0);
        run_gemm(h, Wvg + l * DD, bvg + l * D_, vg, S_, D_, D_, 0);
        glb_attn_kernel<<<dim3(NCLS_, H_), 256>>>(qg, kg, vg, clss, mask_src, outb);

        // output projection + residual LN
        run_gemm(outb, Wo + l * DD, bo + l * D_, tmp, S_, D_, D_, 0);
        add_ln_kernel<<<S_, 256>>>(h, tmp, ln1_s + l * D_, ln1_b + l * D_);

        // feed-forward
        run_gemm(h,  Wf1 + (size_t)l * D_ * FF_, bf1 + l * FF_, ff,  S_, FF_, D_, 1);
        run_gemm(ff, Wf2 + (size_t)l * D_ * FF_, bf2 + l * D_,  tmp, S_, D_, FF_, 0);
        add_ln_kernel<<<S_, 256>>>(h, tmp, ln2_s + l * D_, ln2_b + l * D_);
    }

    cudaMemcpyAsync(d_out, h, (size_t)out_size * sizeof(float), cudaMemcpyDeviceToDevice);
}

// round 15
// speedup vs baseline: 1.1865x; 1.0519x over previous
#include <cuda_runtime.h>
#include <math.h>
#include <stdint.h>

#define S_    4096
#define D_    768
#define H_    12
#define HD_   64
#define NCLS_ 64
#define FF_   3072
#define WIN_  256
#define LAYERS_ 2

// ---------------- scratch (static device globals; no allocation) ----------------
__device__ float g_h  [S_*D_];
__device__ float g_q  [S_*D_];
__device__ float g_k  [S_*D_];
__device__ float g_v  [S_*D_];
__device__ float g_kg [S_*D_];
__device__ float g_vg [S_*D_];
__device__ float g_out[S_*D_];
__device__ float g_tmp[S_*D_];
__device__ float g_ff [S_*FF_];
__device__ float g_hg [NCLS_*D_];
__device__ float g_qg [NCLS_*D_];
__device__ int   g_glb[S_];

// ---------------- fp32 SGEMM core: 64x128 tile, 128 threads, BK=16 ----------------
#define BK_   16
#define SAS_  68    /* padded A-tile k-row stride (floats): 64 rows + 4 pad */
#define NBAT_ 5

#define LOADFRAG_(af, bf, as, bs, kk)                                                        \
    *reinterpret_cast<float4*>(af)       = *reinterpret_cast<const float4*>((as) + (kk) * SAS_ + ty * 8);     \
    *reinterpret_cast<float4*>((af) + 4) = *reinterpret_cast<const float4*>((as) + (kk) * SAS_ + ty * 8 + 4); \
    *reinterpret_cast<float4*>(bf)       = *reinterpret_cast<const float4*>((bs) + (kk) * 128 + tx * 8);      \
    *reinterpret_cast<float4*>((bf) + 4) = *reinterpret_cast<const float4*>((bs) + (kk) * 128 + tx * 8 + 4);

#define FMA88_(af, bf)                                       \
    _Pragma("unroll")                                        \
    for (int i_ = 0; i_ < 8; i_++)                           \
        _Pragma("unroll")                                    \
        for (int j_ = 0; j_ < 8; j_++)                       \
            acc[i_][j_] = fmaf((af)[i_], (bf)[j_], acc[i_][j_]);

struct GemmArgs {
    const float* B[NBAT_];
    const float* bias[NBAT_];
    float*       C[NBAT_];
};

// shared body: computes one 64x128 tile of C = A @ B + bias (+gelu)
template <bool GELU>
static __device__ __forceinline__ void gemm_body(
    const float* __restrict__ A, const float* __restrict__ Bg,
    const float* __restrict__ bias, float* __restrict__ C,
    int M, int N, int K)
{
    __shared__ float As[2][BK_ * SAS_];
    __shared__ float Bs[2][BK_ * 128];
    const int tid = threadIdx.x;
    const int tx = tid & 15;
    const int ty = tid >> 4;
    const int blockRow = blockIdx.y * 64;
    const int blockCol = blockIdx.x * 128;
    const int aRow = tid >> 1;
    const int aCol = (tid & 1) * 8;
    const int bRow = tid >> 3;
    const int bCol = (tid & 7) * 16;

    float acc[8][8];
#pragma unroll
    for (int i = 0; i < 8; i++)
#pragma unroll
        for (int j = 0; j < 8; j++) acc[i][j] = 0.f;

    const float* Ap = A + (size_t)(blockRow + aRow) * K + aCol;
    const float* Bp = Bg + (size_t)bRow * N + blockCol + bCol;
    const bool aOk = (blockRow + aRow) < M;

    float4 pa0, pa1, pb[4];
    pa0 = make_float4(0.f, 0.f, 0.f, 0.f); pa1 = pa0;
    if (aOk) { pa0 = *reinterpret_cast<const float4*>(Ap);
               pa1 = *reinterpret_cast<const float4*>(Ap + 4); }
#pragma unroll
    for (int c = 0; c < 4; c++)
        pb[c] = *reinterpret_cast<const float4*>(Bp + c * 4);
    {
        float* as = As[0];
        as[(aCol + 0) * SAS_ + aRow] = pa0.x;
        as[(aCol + 1) * SAS_ + aRow] = pa0.y;
        as[(aCol + 2) * SAS_ + aRow] = pa0.z;
        as[(aCol + 3) * SAS_ + aRow] = pa0.w;
        as[(aCol + 4) * SAS_ + aRow] = pa1.x;
        as[(aCol + 5) * SAS_ + aRow] = pa1.y;
        as[(aCol + 6) * SAS_ + aRow] = pa1.z;
        as[(aCol + 7) * SAS_ + aRow] = pa1.w;
#pragma unroll
        for (int c = 0; c < 4; c++)
            *reinterpret_cast<float4*>(Bs[0] + bRow * 128 + bCol + c * 4) = pb[c];
    }
    __syncthreads();

    int s = 0;
    for (int k0 = BK_; k0 < K; k0 += BK_) {
        pa0 = make_float4(0.f, 0.f, 0.f, 0.f); pa1 = pa0;
        if (aOk) { pa0 = *reinterpret_cast<const float4*>(Ap + k0);
                   pa1 = *reinterpret_cast<const float4*>(Ap + k0 + 4); }
#pragma unroll
        for (int c = 0; c < 4; c++)
            pb[c] = *reinterpret_cast<const float4*>(Bp + (size_t)k0 * N + c * 4);

        {
            const float* as = As[s];
            const float* bs = Bs[s];
            float af[2][8], bf[2][8];
            LOADFRAG_(af[0], bf[0], as, bs, 0);
#pragma unroll
            for (int kk = 0; kk < BK_; kk++) {
                const int cur = kk & 1;
                if (kk + 1 < BK_) {
                    LOADFRAG_(af[cur ^ 1], bf[cur ^ 1], as, bs, kk + 1);
                }
                FMA88_(af[cur], bf[cur]);
            }
        }

        float* asn = As[s ^ 1];
        asn[(aCol + 0) * SAS_ + aRow] = pa0.x;
        asn[(aCol + 1) * SAS_ + aRow] = pa0.y;
        asn[(aCol + 2) * SAS_ + aRow] = pa0.z;
        asn[(aCol + 3) * SAS_ + aRow] = pa0.w;
        asn[(aCol + 4) * SAS_ + aRow] = pa1.x;
        asn[(aCol + 5) * SAS_ + aRow] = pa1.y;
        asn[(aCol + 6) * SAS_ + aRow] = pa1.z;
        asn[(aCol + 7) * SAS_ + aRow] = pa1.w;
#pragma unroll
        for (int c = 0; c < 4; c++)
            *reinterpret_cast<float4*>(Bs[s ^ 1] + bRow * 128 + bCol + c * 4) = pb[c];
        __syncthreads();
        s ^= 1;
    }

    {
        const float* as = As[s];
        const float* bs = Bs[s];
        float af[2][8], bf[2][8];
        LOADFRAG_(af[0], bf[0], as, bs, 0);
#pragma unroll
        for (int kk = 0; kk < BK_; kk++) {
            const int cur = kk & 1;
            if (kk + 1 < BK_) {
                LOADFRAG_(af[cur ^ 1], bf[cur ^ 1], as, bs, kk + 1);
            }
            FMA88_(af[cur], bf[cur]);
        }
    }

#pragma unroll
    for (int i = 0; i < 8; i++) {
        int r = blockRow + ty * 8 + i;
        if (r >= M) continue;
        float vals[8];
#pragma unroll
        for (int j = 0; j < 8; j++) {
            int c = blockCol + tx * 8 + j;
            float val = acc[i][j] + bias[c];
            if (GELU) {
                float u = 0.7978845608028654f * (val + 0.044715f * val * val * val);
                float t = 1.f - 2.f / (__expf(2.f * u) + 1.f);
                val = 0.5f * val * (1.f + t);
            }
            vals[j] = val;
        }
        *reinterpret_cast<float4*>(C + (size_t)r * N + blockCol + tx * 8) =
            *reinterpret_cast<const float4*>(vals);
        *reinterpret_cast<float4*>(C + (size_t)r * N + blockCol + tx * 8 + 4) =
            *reinterpret_cast<const float4*>(vals + 4);
    }
}

__global__ __launch_bounds__(128, 4) void sgemm_kernel(
    const float* __restrict__ A, const float* __restrict__ B,
    const float* __restrict__ bias, float* __restrict__ C,
    int M, int N, int K, int act)
{
    if (act == 1) gemm_body<true>(A, B, bias, C, M, N, K);
    else          gemm_body<false>(A, B, bias, C, M, N, K);
}

// batched over blockIdx.z: C[z] = A @ B[z] + bias[z]
__global__ __launch_bounds__(128, 4) void sgemm_batched_kernel(
    const float* __restrict__ A, GemmArgs args, int M, int N, int K)
{
    const int z = blockIdx.z;
    gemm_body<false>(A, args.B[z], args.bias[z], args.C[z], M, N, K);
}

// ---------------- embedding + layernorm ----------------
__global__ __launch_bounds__(256) void embed_ln_kernel(
    const int* __restrict__ x, const int* __restrict__ segs,
    const float* __restrict__ we, const float* __restrict__ pe, const float* __restrict__ te,
    const float* __restrict__ lns, const float* __restrict__ lnb,
    float* __restrict__ hout)
{
    int s = blockIdx.x;
    int tid = threadIdx.x;
    __shared__ float buf[D_];
    __shared__ float red[256];
    int tok = x[s], seg = segs[s];
    float lsum = 0.f;
    for (int d = tid; d < D_; d += 256) {
        float v = we[(size_t)tok * D_ + d] + pe[(size_t)s * D_ + d] + te[(size_t)seg * D_ + d];
        buf[d] = v;
        lsum += v;
    }
    red[tid] = lsum; __syncthreads();
    for (int o = 128; o > 0; o >>= 1) { if (tid < o) red[tid] += red[tid + o]; __syncthreads(); }
    float mean = red[0] / D_;
    __syncthreads();
    float vsum = 0.f;
    for (int d = tid; d < D_; d += 256) { float t = buf[d] - mean; vsum += t * t; }
    red[tid] = vsum; __syncthreads();
    for (int o = 128; o > 0; o >>= 1) { if (tid < o) red[tid] += red[tid + o]; __syncthreads(); }
    float rstd = rsqrtf(red[0] / D_ + 1e-5f);
    for (int d = tid; d < D_; d += 256)
        hout[(size_t)s * D_ + d] = (buf[d] - mean) * rstd * lns[d] + lnb[d];
}

// ---------------- residual add + layernorm (in-place into h) ----------------
__global__ __launch_bounds__(256) void add_ln_kernel(
    float* __restrict__ h, const float* __restrict__ t,
    const float* __restrict__ lns, const float* __restrict__ lnb)
{
    int s = blockIdx.x;
    int tid = threadIdx.x;
    __shared__ float buf[D_];
    __shared__ float red[256];
    float lsum = 0.f;
    for (int d = tid; d < D_; d += 256) {
        float v = h[(size_t)s * D_ + d] + t[(size_t)s * D_ + d];
        buf[d] = v;
        lsum += v;
    }
    red[tid] = lsum; __syncthreads();
    for (int o = 128; o > 0; o >>= 1) { if (tid < o) red[tid] += red[tid + o]; __syncthreads(); }
    float mean = red[0] / D_;
    __syncthreads();
    float vsum = 0.f;
    for (int d = tid; d < D_; d += 256) { float x = buf[d] - mean; vsum += x * x; }
    red[tid] = vsum; __syncthreads();
    for (int o = 128; o > 0; o >>= 1) { if (tid < o) red[tid] += red[tid + o]; __syncthreads(); }
    float rstd = rsqrtf(red[0] / D_ + 1e-5f);
    for (int d = tid; d < D_; d += 256)
        h[(size_t)s * D_ + d] = (buf[d] - mean) * rstd * lns[d] + lnb[d];
}

// ---------------- global flags ----------------
__global__ void zero_flags_kernel(int* f)
{
    int i = blockIdx.x * 256 + threadIdx.x;
    if (i < S_) f[i] = 0;
}
__global__ void set_flags_kernel(const int* __restrict__ clss, int* f)
{
    if (threadIdx.x < NCLS_) f[clss[threadIdx.x]] = 1;
}
__global__ __launch_bounds__(256) void gather_rows_kernel(
    const float* __restrict__ h, const int* __restrict__ clss, float* __restrict__ hg)
{
    int c = blockIdx.x;
    int gp = clss[c];
    for (int d = threadIdx.x; d < D_; d += 256)
        hg[(size_t)c * D_ + d] = h[(size_t)gp * D_ + d];
}

// ================ tiled flash-style band + global-key attention ================
// One block per (64-query chunk, head). 640 keys = 64 global + 576 window,
// in 10 chunks of 64 keys -> smem 70.4KB -> 2 blocks/SM.
#define BKEY_ 64
#define NCH_  10
#define KS_   68
#define VS_   68
#define PS_   72
#define OF_Q  0
#define OF_K  4096                    /* 64*64 Q */
#define OF_V  (OF_K + 64*KS_)         /* 8448 */
#define OF_P  (OF_V + BKEY_*VS_)      /* 12800 */
#define OF_KV (OF_P + BKEY_*PS_)      /* 17408 */
#define OF_SC (OF_KV + BKEY_)         /* 17472 */
#define OF_SI (OF_SC + 64)            /* 17536 */
#define BAND_SMEM ((OF_SI + 64) * 4)  /* 70400 bytes */

__global__ __launch_bounds__(256) void band_attn_tiled_kernel(
    const float* __restrict__ q, const float* __restrict__ k, const float* __restrict__ v,
    const int* __restrict__ clss, const int* __restrict__ mask_src, const int* __restrict__ glb,
    float* __restrict__ out)
{
    extern __shared__ float sm[];
    float* Qsd = sm + OF_Q;          // [d][r]  stride 64
    float* Ksd = sm + OF_K;          // [d][kk] stride KS_
    float* Vs  = sm + OF_V;          // [kk][d] stride VS_
    float* Pkq = sm + OF_P;          // [kk][r] stride PS_
    int*   kvl = (int*)(sm + OF_KV);
    float* ssc = sm + OF_SC;
    float* sin_ = sm + OF_SI;

    const int c = blockIdx.x, hh = blockIdx.y;
    const int s0 = c * 64;
    const int t = threadIdx.x;
    const int w = t >> 5, lane = t & 31;

    for (int idx = t; idx < 64 * 16; idx += 256) {
        const int r = idx >> 4, seg = (idx & 15) * 4;
        const float4 qv = *reinterpret_cast<const float4*>(
            q + ((size_t)(s0 + r) * H_ + hh) * HD_ + seg);
        Qsd[(seg + 0) * 64 + r] = qv.x * 0.125f;
        Qsd[(seg + 1) * 64 + r] = qv.y * 0.125f;
        Qsd[(seg + 2) * 64 + r] = qv.z * 0.125f;
        Qsd[(seg + 3) * 64 + r] = qv.w * 0.125f;
    }

    float mstate = -1e30f, ssum = 0.f;   // live in threads t<64
    float O[8][2];
#pragma unroll
    for (int j = 0; j < 8; j++) { O[j][0] = 0.f; O[j][1] = 0.f; }

    const int tq = t >> 3, tk = t & 7;   // 32 q-groups x 8 k-groups
    const int r0 = tq * 2, kk0 = tk * 8;

    for (int ch = 0; ch < NCH_; ch++) {
        // ---- load K (transposed), V, validity : 64 keys ----
        for (int idx = t; idx < BKEY_ * 16; idx += 256) {
            const int kr = idx >> 4, seg = (idx & 15) * 4;
            const int gi = ch * BKEY_ + kr;
            int p; int val;
            if (gi < NCLS_) {
                p = clss[gi];
                val = (mask_src[p] > 0);
            } else {
                p = s0 + gi - 320;
                val = (p >= 0 && p < S_);
                if (val) val = (mask_src[p] > 0) && (glb[p] == 0);
                if (!val) p = 0;
            }
            if ((idx & 15) == 0) kvl[kr] = val;
            const float4 kv = *reinterpret_cast<const float4*>(
                k + ((size_t)p * H_ + hh) * HD_ + seg);
            Ksd[(seg + 0) * KS_ + kr] = kv.x;
            Ksd[(seg + 1) * KS_ + kr] = kv.y;
            Ksd[(seg + 2) * KS_ + kr] = kv.z;
            Ksd[(seg + 3) * KS_ + kr] = kv.w;
            *reinterpret_cast<float4*>(Vs + kr * VS_ + seg) =
                *reinterpret_cast<const float4*>(v + ((size_t)p * H_ + hh) * HD_ + seg);
        }
        __syncthreads();

        // ---- QK scores: thread computes 2q x 8k ----
        float sc[2][8];
#pragma unroll
        for (int j = 0; j < 2; j++)
#pragma unroll
            for (int i = 0; i < 8; i++) sc[j][i] = 0.f;
#pragma unroll 8
        for (int d = 0; d < 64; d++) {
            const float2 a = *reinterpret_cast<const float2*>(Qsd + d * 64 + r0);
            const float4 b0 = *reinterpret_cast<const float4*>(Ksd + d * KS_ + kk0);
            const float4 b1 = *reinterpret_cast<const float4*>(Ksd + d * KS_ + kk0 + 4);
            const float aa[2] = {a.x, a.y};
            const float bb[8] = {b0.x, b0.y, b0.z, b0.w, b1.x, b1.y, b1.z, b1.w};
#pragma unroll
            for (int j = 0; j < 2; j++)
#pragma unroll
                for (int i = 0; i < 8; i++) sc[j][i] = fmaf(aa[j], bb[i], sc[j][i]);
        }
#pragma unroll
        for (int i = 0; i < 8; i++) {
            const int gi = ch * BKEY_ + kk0 + i;
            const int kvalid = kvl[kk0 + i];
#pragma unroll
            for (int j = 0; j < 2; j++) {
                const int r = r0 + j;
                const bool ok = kvalid &&
                    (gi < NCLS_ || (r >= gi - 576 && r <= gi - 64));
                Pkq[(kk0 + i) * PS_ + r] = ok ? sc[j][i] : -1e30f;
            }
        }
        __syncthreads();

        // ---- online softmax update (threads < 64, one per query) ----
        if (t < 64) {
            float mn = mstate;
            for (int kk = 0; kk < BKEY_; kk++) mn = fmaxf(mn, Pkq[kk * PS_ + t]);
            const float scale = (mn <= -1e29f) ? 1.f : __expf(mstate - mn);
            float ls = 0.f;
            for (int kk = 0; kk < BKEY_; kk++) {
                const float sv = Pkq[kk * PS_ + t];
                const float pv = (sv <= -1e29f) ? 0.f : __expf(sv - mn);
                Pkq[kk * PS_ + t] = pv;
                ls += pv;
            }
            ssum = ssum * scale + ls;
            mstate = mn;
            ssc[t] = scale;
        }
        __syncthreads();

        // ---- PV accumulate: warp handles queries w*8..w*8+7, lane dims {lane, lane+32} ----
        {
#pragma unroll
            for (int j = 0; j < 8; j++) {
                const float scj = ssc[w * 8 + j];
                O[j][0] *= scj; O[j][1] *= scj;
            }
            for (int kk = 0; kk < BKEY_; kk++) {
                const float4 pa = *reinterpret_cast<const float4*>(Pkq + kk * PS_ + w * 8);
                const float4 pb = *reinterpret_cast<const float4*>(Pkq + kk * PS_ + w * 8 + 4);
                const float v0 = Vs[kk * VS_ + lane];
                const float v1 = Vs[kk * VS_ + lane + 32];
                O[0][0] = fmaf(pa.x, v0, O[0][0]); O[0][1] = fmaf(pa.x, v1, O[0][1]);
                O[1][0] = fmaf(pa.y, v0, O[1][0]); O[1][1] = fmaf(pa.y, v1, O[1][1]);
                O[2][0] = fmaf(pa.z, v0, O[2][0]); O[2][1] = fmaf(pa.z, v1, O[2][1]);
                O[3][0] = fmaf(pa.w, v0, O[3][0]); O[3][1] = fmaf(pa.w, v1, O[3][1]);
                O[4][0] = fmaf(pb.x, v0, O[4][0]); O[4][1] = fmaf(pb.x, v1, O[4][1]);
                O[5][0] = fmaf(pb.y, v0, O[5][0]); O[5][1] = fmaf(pb.y, v1, O[5][1]);
                O[6][0] = fmaf(pb.z, v0, O[6][0]); O[6][1] = fmaf(pb.z, v1, O[6][1]);
                O[7][0] = fmaf(pb.w, v0, O[7][0]); O[7][1] = fmaf(pb.w, v1, O[7][1]);
            }
        }
        __syncthreads();
    }

    if (t < 64) sin_[t] = 1.f / ssum;
    __syncthreads();
#pragma unroll
    for (int j = 0; j < 8; j++) {
        const int qr = w * 8 + j;
        const float inv = sin_[qr];
        float* op = out + ((size_t)(s0 + qr) * H_ + hh) * HD_;
        op[lane]      = O[j][0] * inv;
        op[lane + 32] = O[j][1] * inv;
    }
}

// ---------------- global-query full attention: one block per (c, head) ----------------
__global__ __launch_bounds__(256) void glb_attn_kernel(
    const float* __restrict__ qg, const float* __restrict__ kg, const float* __restrict__ vg,
    const int* __restrict__ clss, const int* __restrict__ mask_src,
    float* __restrict__ out)
{
    const int c = blockIdx.x;
    const int h = blockIdx.y;
    __shared__ float qs[HD_];
    __shared__ float sc[S_];
    __shared__ float red[256];
    const int tid = threadIdx.x;
    const int lane = tid & 31;
    const int w = tid >> 5;

    if (tid < HD_) qs[tid] = qg[((size_t)c * H_ + h) * HD_ + tid] * 0.125f;
    __syncthreads();

    for (int p = w; p < S_; p += 8) {
        const float* kp = kg + ((size_t)p * H_ + h) * HD_;
        float sdot = qs[lane] * kp[lane] + qs[lane + 32] * kp[lane + 32];
#pragma unroll
        for (int o = 16; o > 0; o >>= 1) sdot += __shfl_xor_sync(0xffffffffu, sdot, o);
        if (lane == 0) sc[p] = (mask_src[p] > 0) ? sdot : -1e30f;
    }
    __syncthreads();

    float m = -1e30f;
    for (int p = tid; p < S_; p += 256) m = fmaxf(m, sc[p]);
    red[tid] = m; __syncthreads();
    for (int o = 128; o > 0; o >>= 1) { if (tid < o) red[tid] = fmaxf(red[tid], red[tid + o]); __syncthreads(); }
    m = red[0];
    __syncthreads();
    float sum = 0.f;
    for (int p = tid; p < S_; p += 256) { float e = __expf(sc[p] - m); sc[p] = e; sum += e; }
    red[tid] = sum; __syncthreads();
    for (int o = 128; o > 0; o >>= 1) { if (tid < o) red[tid] += red[tid + o]; __syncthreads(); }
    float inv = 1.f / red[0];
    __syncthreads();

    int d = tid & 63, quarter = tid >> 6;
    float acc = 0.f;
    for (int p = quarter; p < S_; p += 4)
        acc += sc[p] * vg[((size_t)p * H_ + h) * HD_ + d];
    red[tid] = acc; __syncthreads();
    if (tid < 64) {
        float o = (red[tid] + red[tid + 64] + red[tid + 128] + red[tid + 192]) * inv;
        int gp = clss[c];
        out[((size_t)gp * H_ + h) * HD_ + tid] = o;
    }
}

// ---------------- driver ----------------
static void run_gemm(const float* A, const float* B, const float* bias, float* C,
                     int M, int N, int K, int act)
{
    dim3 grid(N / 128, (M + 63) / 64);
    sgemm_kernel<<<grid, 128>>>(A, B, bias, C, M, N, K, act);
}

extern "C" void kernel_launch(void* const* d_in, const int* in_sizes, int n_in,
                              void* d_out, int out_size)
{
    (void)in_sizes; (void)n_in;
    const int*   x        = (const int*)d_in[0];
    const int*   mask_src = (const int*)d_in[1];
    const int*   clss     = (const int*)d_in[2];
    const int*   segs     = (const int*)d_in[3];
    const float* word_emb = (const float*)d_in[4];
    const float* pos_emb  = (const float*)d_in[5];
    const float* type_emb = (const float*)d_in[6];
    const float* ln_e_s   = (const float*)d_in[7];
    const float* ln_e_b   = (const float*)d_in[8];
    const float* Wq  = (const float*)d_in[9];   const float* bq  = (const float*)d_in[10];
    const float* Wk  = (const float*)d_in[11];  const float* bk  = (const float*)d_in[12];
    const float* Wv  = (const float*)d_in[13];  const float* bv  = (const float*)d_in[14];
    const float* Wqg = (const float*)d_in[15];  const float* bqg = (const float*)d_in[16];
    const float* Wkg = (const float*)d_in[17];  const float* bkg = (const float*)d_in[18];
    const float* Wvg = (const float*)d_in[19];  const float* bvg = (const float*)d_in[20];
    const float* Wo  = (const float*)d_in[21];  const float* bo  = (const float*)d_in[22];
    const float* ln1_s = (const float*)d_in[23]; const float* ln1_b = (const float*)d_in[24];
    const float* Wf1 = (const float*)d_in[25];  const float* bf1 = (const float*)d_in[26];
    const float* Wf2 = (const float*)d_in[27];  const float* bf2 = (const float*)d_in[28];
    const float* ln2_s = (const float*)d_in[29]; const float* ln2_b = (const float*)d_in[30];

    float *h, *q, *k, *v, *kg, *vg, *outb, *tmp, *ff, *hg, *qg;
    int* glb;
    cudaGetSymbolAddress((void**)&h,    g_h);
    cudaGetSymbolAddress((void**)&q,    g_q);
    cudaGetSymbolAddress((void**)&k,    g_k);
    cudaGetSymbolAddress((void**)&v,    g_v);
    cudaGetSymbolAddress((void**)&kg,   g_kg);
    cudaGetSymbolAddress((void**)&vg,   g_vg);
    cudaGetSymbolAddress((void**)&outb, g_out);
    cudaGetSymbolAddress((void**)&tmp,  g_tmp);
    cudaGetSymbolAddress((void**)&ff,   g_ff);
    cudaGetSymbolAddress((void**)&hg,   g_hg);
    cudaGetSymbolAddress((void**)&qg,   g_qg);
    cudaGetSymbolAddress((void**)&glb,  g_glb);

    cudaFuncSetAttribute(band_attn_tiled_kernel,
                         cudaFuncAttributeMaxDynamicSharedMemorySize, BAND_SMEM);

    // embedding + LN
    embed_ln_kernel<<<S_, 256>>>(x, segs, word_emb, pos_emb, type_emb, ln_e_s, ln_e_b, h);

    // global flags
    zero_flags_kernel<<<(S_ + 255) / 256, 256>>>(glb);
    set_flags_kernel<<<1, 64>>>(clss, glb);

    const size_t DD = (size_t)D_ * D_;
    for (int l = 0; l < LAYERS_; l++) {
        // Q K V Kg Vg projections: one batched launch (shared A = h)
        {
            GemmArgs ga;
            ga.B[0] = Wq  + l * DD; ga.bias[0] = bq  + l * D_; ga.C[0] = q;
            ga.B[1] = Wk  + l * DD; ga.bias[1] = bk  + l * D_; ga.C[1] = k;
            ga.B[2] = Wv  + l * DD; ga.bias[2] = bv  + l * D_; ga.C[2] = v;
            ga.B[3] = Wkg + l * DD; ga.bias[3] = bkg + l * D_; ga.C[3] = kg;
            ga.B[4] = Wvg + l * DD; ga.bias[4] = bvg + l * D_; ga.C[4] = vg;
            dim3 grid(D_ / 128, S_ / 64, NBAT_);
            sgemm_batched_kernel<<<grid, 128>>>(h, ga, S_, D_, D_);
        }

        // tiled band + global-key attention (writes all rows of outb)
        band_attn_tiled_kernel<<<dim3(S_ / 64, H_), 256, BAND_SMEM>>>(
            q, k, v, clss, mask_src, glb, outb);

        // global-query path
        gather_rows_kernel<<<NCLS_, 256>>>(h, clss, hg);
        run_gemm(hg, Wqg + l * DD, bqg + l * D_, qg, NCLS_, D_, D_, 0);
        glb_attn_kernel<<<dim3(NCLS_, H_), 256>>>(qg, kg, vg, clss, mask_src, outb);

        // output projection + residual LN
        run_gemm(outb, Wo + l * DD, bo + l * D_, tmp, S_, D_, D_, 0);
        add_ln_kernel<<<S_, 256>>>(h, tmp, ln1_s + l * D_, ln1_b + l * D_);

        // feed-forward
        run_gemm(h,  Wf1 + (size_t)l * D_ * FF_, bf1 + l * FF_, ff,  S_, FF_, D_, 1);
        run_gemm(ff, Wf2 + (size_t)l * D_ * FF_, bf2 + l * D_,  tmp, S_, D_, FF_, 0);
        add_ln_kernel<<<S_, 256>>>(h, tmp, ln2_s + l * D_, ln2_b + l * D_);
    }

    cudaMemcpyAsync(d_out, h, (size_t)out_size * sizeof(float), cudaMemcpyDeviceToDevice);
}

// round 16
// speedup vs baseline: 1.1927x; 1.0053x over previous
#include <cuda_runtime.h>
#include <math.h>
#include <stdint.h>

#define S_    4096
#define D_    768
#define H_    12
#define HD_   64
#define NCLS_ 64
#define FF_   3072
#define WIN_  256
#define LAYERS_ 2

typedef unsigned long long u64;

// ---------------- scratch (static device globals; no allocation) ----------------
__device__ float g_h  [S_*D_];
__device__ float g_q  [S_*D_];
__device__ float g_k  [S_*D_];
__device__ float g_v  [S_*D_];
__device__ float g_kg [S_*D_];
__device__ float g_vg [S_*D_];
__device__ float g_out[S_*D_];
__device__ float g_tmp[S_*D_];
__device__ float g_ff [S_*FF_];
__device__ float g_hg [NCLS_*D_];
__device__ float g_qg [NCLS_*D_];
__device__ int   g_glb[S_];

// ---------------- packed f32x2 helpers ----------------
static __device__ __forceinline__ u64 dup_f32x2(float x) {
    u64 r; asm("mov.b64 %0, {%1, %1};" : "=l"(r) : "f"(x)); return r;
}
static __device__ __forceinline__ void ffma2(u64& c, u64 a, u64 b) {
    asm("fma.rn.f32x2 %0, %1, %2, %0;" : "+l"(c) : "l"(a), "l"(b));
}
static __device__ __forceinline__ void unpack2(float& lo, float& hi, u64 v) {
    asm("mov.b64 {%0, %1}, %2;" : "=f"(lo), "=f"(hi) : "l"(v));
}

// ---------------- fp32 SGEMM core: 64x128 tile, 128 threads, BK=16 ----------------
// Inner loop on packed fma.rn.f32x2 (accumulators = 32 register pairs).
#define BK_   16
#define SAS_  68    /* padded A-tile k-row stride (floats): 64 rows + 4 pad */
#define NBAT_ 5

#define LOADFRAG_(af, bfp, as, bs, kk)                                                        \
    *reinterpret_cast<float4*>(af)       = *reinterpret_cast<const float4*>((as) + (kk) * SAS_ + ty * 8);     \
    *reinterpret_cast<float4*>((af) + 4) = *reinterpret_cast<const float4*>((as) + (kk) * SAS_ + ty * 8 + 4); \
    *reinterpret_cast<ulonglong2*>(bfp)       = *reinterpret_cast<const ulonglong2*>((bs) + (kk) * 128 + tx * 8);     \
    *reinterpret_cast<ulonglong2*>((bfp) + 2) = *reinterpret_cast<const ulonglong2*>((bs) + (kk) * 128 + tx * 8 + 4);

#define FMA88_(af, bfp)                                      \
    _Pragma("unroll")                                        \
    for (int i_ = 0; i_ < 8; i_++) {                         \
        const u64 ad_ = dup_f32x2((af)[i_]);                 \
        _Pragma("unroll")                                    \
        for (int jp_ = 0; jp_ < 4; jp_++)                    \
            ffma2(acc2[i_][jp_], ad_, (bfp)[jp_]);           \
    }

struct GemmArgs {
    const float* B[NBAT_];
    const float* bias[NBAT_];
    float*       C[NBAT_];
};

// shared body: computes one 64x128 tile of C = A @ B + bias (+gelu)
template <bool GELU>
static __device__ __forceinline__ void gemm_body(
    const float* __restrict__ A, const float* __restrict__ Bg,
    const float* __restrict__ bias, float* __restrict__ C,
    int M, int N, int K)
{
    __shared__ float As[2][BK_ * SAS_];
    __shared__ float Bs[2][BK_ * 128];
    const int tid = threadIdx.x;
    const int tx = tid & 15;
    const int ty = tid >> 4;
    const int blockRow = blockIdx.y * 64;
    const int blockCol = blockIdx.x * 128;
    const int aRow = tid >> 1;
    const int aCol = (tid & 1) * 8;
    const int bRow = tid >> 3;
    const int bCol = (tid & 7) * 16;

    u64 acc2[8][4];
#pragma unroll
    for (int i = 0; i < 8; i++)
#pragma unroll
        for (int jp = 0; jp < 4; jp++) acc2[i][jp] = 0ull;

    const float* Ap = A + (size_t)(blockRow + aRow) * K + aCol;
    const float* Bp = Bg + (size_t)bRow * N + blockCol + bCol;
    const bool aOk = (blockRow + aRow) < M;

    float4 pa0, pa1, pb[4];
    pa0 = make_float4(0.f, 0.f, 0.f, 0.f); pa1 = pa0;
    if (aOk) { pa0 = *reinterpret_cast<const float4*>(Ap);
               pa1 = *reinterpret_cast<const float4*>(Ap + 4); }
#pragma unroll
    for (int c = 0; c < 4; c++)
        pb[c] = *reinterpret_cast<const float4*>(Bp + c * 4);
    {
        float* as = As[0];
        as[(aCol + 0) * SAS_ + aRow] = pa0.x;
        as[(aCol + 1) * SAS_ + aRow] = pa0.y;
        as[(aCol + 2) * SAS_ + aRow] = pa0.z;
        as[(aCol + 3) * SAS_ + aRow] = pa0.w;
        as[(aCol + 4) * SAS_ + aRow] = pa1.x;
        as[(aCol + 5) * SAS_ + aRow] = pa1.y;
        as[(aCol + 6) * SAS_ + aRow] = pa1.z;
        as[(aCol + 7) * SAS_ + aRow] = pa1.w;
#pragma unroll
        for (int c = 0; c < 4; c++)
            *reinterpret_cast<float4*>(Bs[0] + bRow * 128 + bCol + c * 4) = pb[c];
    }
    __syncthreads();

    int s = 0;
    for (int k0 = BK_; k0 < K; k0 += BK_) {
        pa0 = make_float4(0.f, 0.f, 0.f, 0.f); pa1 = pa0;
        if (aOk) { pa0 = *reinterpret_cast<const float4*>(Ap + k0);
                   pa1 = *reinterpret_cast<const float4*>(Ap + k0 + 4); }
#pragma unroll
        for (int c = 0; c < 4; c++)
            pb[c] = *reinterpret_cast<const float4*>(Bp + (size_t)k0 * N + c * 4);

        {
            const float* as = As[s];
            const float* bs = Bs[s];
            float af[2][8];
            u64 bfp[2][4];
            LOADFRAG_(af[0], bfp[0], as, bs, 0);
#pragma unroll
            for (int kk = 0; kk < BK_; kk++) {
                const int cur = kk & 1;
                if (kk + 1 < BK_) {
                    LOADFRAG_(af[cur ^ 1], bfp[cur ^ 1], as, bs, kk + 1);
                }
                FMA88_(af[cur], bfp[cur]);
            }
        }

        float* asn = As[s ^ 1];
        asn[(aCol + 0) * SAS_ + aRow] = pa0.x;
        asn[(aCol + 1) * SAS_ + aRow] = pa0.y;
        asn[(aCol + 2) * SAS_ + aRow] = pa0.z;
        asn[(aCol + 3) * SAS_ + aRow] = pa0.w;
        asn[(aCol + 4) * SAS_ + aRow] = pa1.x;
        asn[(aCol + 5) * SAS_ + aRow] = pa1.y;
        asn[(aCol + 6) * SAS_ + aRow] = pa1.z;
        asn[(aCol + 7) * SAS_ + aRow] = pa1.w;
#pragma unroll
        for (int c = 0; c < 4; c++)
            *reinterpret_cast<float4*>(Bs[s ^ 1] + bRow * 128 + bCol + c * 4) = pb[c];
        __syncthreads();
        s ^= 1;
    }

    {
        const float* as = As[s];
        const float* bs = Bs[s];
        float af[2][8];
        u64 bfp[2][4];
        LOADFRAG_(af[0], bfp[0], as, bs, 0);
#pragma unroll
        for (int kk = 0; kk < BK_; kk++) {
            const int cur = kk & 1;
            if (kk + 1 < BK_) {
                LOADFRAG_(af[cur ^ 1], bfp[cur ^ 1], as, bs, kk + 1);
            }
            FMA88_(af[cur], bfp[cur]);
        }
    }

#pragma unroll
    for (int i = 0; i < 8; i++) {
        int r = blockRow + ty * 8 + i;
        if (r >= M) continue;
        float vals[8];
#pragma unroll
        for (int jp = 0; jp < 4; jp++) {
            float v0, v1;
            unpack2(v0, v1, acc2[i][jp]);
            vals[jp * 2 + 0] = v0;
            vals[jp * 2 + 1] = v1;
        }
#pragma unroll
        for (int j = 0; j < 8; j++) {
            int c = blockCol + tx * 8 + j;
            float val = vals[j] + bias[c];
            if (GELU) {
                float u = 0.7978845608028654f * (val + 0.044715f * val * val * val);
                float t = 1.f - 2.f / (__expf(2.f * u) + 1.f);
                val = 0.5f * val * (1.f + t);
            }
            vals[j] = val;
        }
        *reinterpret_cast<float4*>(C + (size_t)r * N + blockCol + tx * 8) =
            *reinterpret_cast<const float4*>(vals);
        *reinterpret_cast<float4*>(C + (size_t)r * N + blockCol + tx * 8 + 4) =
            *reinterpret_cast<const float4*>(vals + 4);
    }
}

__global__ __launch_bounds__(128, 4) void sgemm_kernel(
    const float* __restrict__ A, const float* __restrict__ B,
    const float* __restrict__ bias, float* __restrict__ C,
    int M, int N, int K, int act)
{
    if (act == 1) gemm_body<true>(A, B, bias, C, M, N, K);
    else          gemm_body<false>(A, B, bias, C, M, N, K);
}

// batched over blockIdx.z: C[z] = A @ B[z] + bias[z]
__global__ __launch_bounds__(128, 4) void sgemm_batched_kernel(
    const float* __restrict__ A, GemmArgs args, int M, int N, int K)
{
    const int z = blockIdx.z;
    gemm_body<false>(A, args.B[z], args.bias[z], args.C[z], M, N, K);
}

// ---------------- embedding + layernorm ----------------
__global__ __launch_bounds__(256) void embed_ln_kernel(
    const int* __restrict__ x, const int* __restrict__ segs,
    const float* __restrict__ we, const float* __restrict__ pe, const float* __restrict__ te,
    const float* __restrict__ lns, const float* __restrict__ lnb,
    float* __restrict__ hout)
{
    int s = blockIdx.x;
    int tid = threadIdx.x;
    __shared__ float buf[D_];
    __shared__ float red[256];
    int tok = x[s], seg = segs[s];
    float lsum = 0.f;
    for (int d = tid; d < D_; d += 256) {
        float v = we[(size_t)tok * D_ + d] + pe[(size_t)s * D_ + d] + te[(size_t)seg * D_ + d];
        buf[d] = v;
        lsum += v;
    }
    red[tid] = lsum; __syncthreads();
    for (int o = 128; o > 0; o >>= 1) { if (tid < o) red[tid] += red[tid + o]; __syncthreads(); }
    float mean = red[0] / D_;
    __syncthreads();
    float vsum = 0.f;
    for (int d = tid; d < D_; d += 256) { float t = buf[d] - mean; vsum += t * t; }
    red[tid] = vsum; __syncthreads();
    for (int o = 128; o > 0; o >>= 1) { if (tid < o) red[tid] += red[tid + o]; __syncthreads(); }
    float rstd = rsqrtf(red[0] / D_ + 1e-5f);
    for (int d = tid; d < D_; d += 256)
        hout[(size_t)s * D_ + d] = (buf[d] - mean) * rstd * lns[d] + lnb[d];
}

// ---------------- residual add + layernorm (in-place into h) ----------------
__global__ __launch_bounds__(256) void add_ln_kernel(
    float* __restrict__ h, const float* __restrict__ t,
    const float* __restrict__ lns, const float* __restrict__ lnb)
{
    int s = blockIdx.x;
    int tid = threadIdx.x;
    __shared__ float buf[D_];
    __shared__ float red[256];
    float lsum = 0.f;
    for (int d = tid; d < D_; d += 256) {
        float v = h[(size_t)s * D_ + d] + t[(size_t)s * D_ + d];
        buf[d] = v;
        lsum += v;
    }
    red[tid] = lsum; __syncthreads();
    for (int o = 128; o > 0; o >>= 1) { if (tid < o) red[tid] += red[tid + o]; __syncthreads(); }
    float mean = red[0] / D_;
    __syncthreads();
    float vsum = 0.f;
    for (int d = tid; d < D_; d += 256) { float x = buf[d] - mean; vsum += x * x; }
    red[tid] = vsum; __syncthreads();
    for (int o = 128; o > 0; o >>= 1) { if (tid < o) red[tid] += red[tid + o]; __syncthreads(); }
    float rstd = rsqrtf(red[0] / D_ + 1e-5f);
    for (int d = tid; d < D_; d += 256)
        h[(size_t)s * D_ + d] = (buf[d] - mean) * rstd * lns[d] + lnb[d];
}

// ---------------- global flags ----------------
__global__ void zero_flags_kernel(int* f)
{
    int i = blockIdx.x * 256 + threadIdx.x;
    if (i < S_) f[i] = 0;
}
__global__ void set_flags_kernel(const int* __restrict__ clss, int* f)
{
    if (threadIdx.x < NCLS_) f[clss[threadIdx.x]] = 1;
}
__global__ __launch_bounds__(256) void gather_rows_kernel(
    const float* __restrict__ h, const int* __restrict__ clss, float* __restrict__ hg)
{
    int c = blockIdx.x;
    int gp = clss[c];
    for (int d = threadIdx.x; d < D_; d += 256)
        hg[(size_t)c * D_ + d] = h[(size_t)gp * D_ + d];
}

// ================ tiled flash-style band + global-key attention ================
// One block per (64-query chunk, head). 640 keys = 64 global + 576 window,
// in 10 chunks of 64 keys -> smem 70.4KB -> 2 blocks/SM.
#define BKEY_ 64
#define NCH_  10
#define KS_   68
#define VS_   68
#define PS_   72
#define OF_Q  0
#define OF_K  4096                    /* 64*64 Q */
#define OF_V  (OF_K + 64*KS_)         /* 8448 */
#define OF_P  (OF_V + BKEY_*VS_)      /* 12800 */
#define OF_KV (OF_P + BKEY_*PS_)      /* 17408 */
#define OF_SC (OF_KV + BKEY_)         /* 17472 */
#define OF_SI (OF_SC + 64)            /* 17536 */
#define BAND_SMEM ((OF_SI + 64) * 4)  /* 70400 bytes */

__global__ __launch_bounds__(256) void band_attn_tiled_kernel(
    const float* __restrict__ q, const float* __restrict__ k, const float* __restrict__ v,
    const int* __restrict__ clss, const int* __restrict__ mask_src, const int* __restrict__ glb,
    float* __restrict__ out)
{
    extern __shared__ float sm[];
    float* Qsd = sm + OF_Q;          // [d][r]  stride 64
    float* Ksd = sm + OF_K;          // [d][kk] stride KS_
    float* Vs  = sm + OF_V;          // [kk][d] stride VS_
    float* Pkq = sm + OF_P;          // [kk][r] stride PS_
    int*   kvl = (int*)(sm + OF_KV);
    float* ssc = sm + OF_SC;
    float* sin_ = sm + OF_SI;

    const int c = blockIdx.x, hh = blockIdx.y;
    const int s0 = c * 64;
    const int t = threadIdx.x;
    const int w = t >> 5, lane = t & 31;

    for (int idx = t; idx < 64 * 16; idx += 256) {
        const int r = idx >> 4, seg = (idx & 15) * 4;
        const float4 qv = *reinterpret_cast<const float4*>(
            q + ((size_t)(s0 + r) * H_ + hh) * HD_ + seg);
        Qsd[(seg + 0) * 64 + r] = qv.x * 0.125f;
        Qsd[(seg + 1) * 64 + r] = qv.y * 0.125f;
        Qsd[(seg + 2) * 64 + r] = qv.z * 0.125f;
        Qsd[(seg + 3) * 64 + r] = qv.w * 0.125f;
    }

    float mstate = -1e30f, ssum = 0.f;   // live in threads t<64
    float O[8][2];
#pragma unroll
    for (int j = 0; j < 8; j++) { O[j][0] = 0.f; O[j][1] = 0.f; }

    const int tq = t >> 3, tk = t & 7;   // 32 q-groups x 8 k-groups
    const int r0 = tq * 2, kk0 = tk * 8;

    for (int ch = 0; ch < NCH_; ch++) {
        // ---- load K (transposed), V, validity : 64 keys ----
        for (int idx = t; idx < BKEY_ * 16; idx += 256) {
            const int kr = idx >> 4, seg = (idx & 15) * 4;
            const int gi = ch * BKEY_ + kr;
            int p; int val;
            if (gi < NCLS_) {
                p = clss[gi];
                val = (mask_src[p] > 0);
            } else {
                p = s0 + gi - 320;
                val = (p >= 0 && p < S_);
                if (val) val = (mask_src[p] > 0) && (glb[p] == 0);
                if (!val) p = 0;
            }
            if ((idx & 15) == 0) kvl[kr] = val;
            const float4 kv = *reinterpret_cast<const float4*>(
                k + ((size_t)p * H_ + hh) * HD_ + seg);
            Ksd[(seg + 0) * KS_ + kr] = kv.x;
            Ksd[(seg + 1) * KS_ + kr] = kv.y;
            Ksd[(seg + 2) * KS_ + kr] = kv.z;
            Ksd[(seg + 3) * KS_ + kr] = kv.w;
            *reinterpret_cast<float4*>(Vs + kr * VS_ + seg) =
                *reinterpret_cast<const float4*>(v + ((size_t)p * H_ + hh) * HD_ + seg);
        }
        __syncthreads();

        // ---- QK scores: thread computes 2q x 8k ----
        float sc[2][8];
#pragma unroll
        for (int j = 0; j < 2; j++)
#pragma unroll
            for (int i = 0; i < 8; i++) sc[j][i] = 0.f;
#pragma unroll 8
        for (int d = 0; d < 64; d++) {
            const float2 a = *reinterpret_cast<const float2*>(Qsd + d * 64 + r0);
            const float4 b0 = *reinterpret_cast<const float4*>(Ksd + d * KS_ + kk0);
            const float4 b1 = *reinterpret_cast<const float4*>(Ksd + d * KS_ + kk0 + 4);
            const float aa[2] = {a.x, a.y};
            const float bb[8] = {b0.x, b0.y, b0.z, b0.w, b1.x, b1.y, b1.z, b1.w};
#pragma unroll
            for (int j = 0; j < 2; j++)
#pragma unroll
                for (int i = 0; i < 8; i++) sc[j][i] = fmaf(aa[j], bb[i], sc[j][i]);
        }
#pragma unroll
        for (int i = 0; i < 8; i++) {
            const int gi = ch * BKEY_ + kk0 + i;
            const int kvalid = kvl[kk0 + i];
#pragma unroll
            for (int j = 0; j < 2; j++) {
                const int r = r0 + j;
                const bool ok = kvalid &&
                    (gi < NCLS_ || (r >= gi - 576 && r <= gi - 64));
                Pkq[(kk0 + i) * PS_ + r] = ok ? sc[j][i] : -1e30f;
            }
        }
        __syncthreads();

        // ---- online softmax update (threads < 64, one per query) ----
        if (t < 64) {
            float mn = mstate;
            for (int kk = 0; kk < BKEY_; kk++) mn = fmaxf(mn, Pkq[kk * PS_ + t]);
            const float scale = (mn <= -1e29f) ? 1.f : __expf(mstate - mn);
            float ls = 0.f;
            for (int kk = 0; kk < BKEY_; kk++) {
                const float sv = Pkq[kk * PS_ + t];
                const float pv = (sv <= -1e29f) ? 0.f : __expf(sv - mn);
                Pkq[kk * PS_ + t] = pv;
                ls += pv;
            }
            ssum = ssum * scale + ls;
            mstate = mn;
            ssc[t] = scale;
        }
        __syncthreads();

        // ---- PV accumulate: warp handles queries w*8..w*8+7, lane dims {lane, lane+32} ----
        {
#pragma unroll
            for (int j = 0; j < 8; j++) {
                const float scj = ssc[w * 8 + j];
                O[j][0] *= scj; O[j][1] *= scj;
            }
            for (int kk = 0; kk < BKEY_; kk++) {
                const float4 pa = *reinterpret_cast<const float4*>(Pkq + kk * PS_ + w * 8);
                const float4 pb = *reinterpret_cast<const float4*>(Pkq + kk * PS_ + w * 8 + 4);
                const float v0 = Vs[kk * VS_ + lane];
                const float v1 = Vs[kk * VS_ + lane + 32];
                O[0][0] = fmaf(pa.x, v0, O[0][0]); O[0][1] = fmaf(pa.x, v1, O[0][1]);
                O[1][0] = fmaf(pa.y, v0, O[1][0]); O[1][1] = fmaf(pa.y, v1, O[1][1]);
                O[2][0] = fmaf(pa.z, v0, O[2][0]); O[2][1] = fmaf(pa.z, v1, O[2][1]);
                O[3][0] = fmaf(pa.w, v0, O[3][0]); O[3][1] = fmaf(pa.w, v1, O[3][1]);
                O[4][0] = fmaf(pb.x, v0, O[4][0]); O[4][1] = fmaf(pb.x, v1, O[4][1]);
                O[5][0] = fmaf(pb.y, v0, O[5][0]); O[5][1] = fmaf(pb.y, v1, O[5][1]);
                O[6][0] = fmaf(pb.z, v0, O[6][0]); O[6][1] = fmaf(pb.z, v1, O[6][1]);
                O[7][0] = fmaf(pb.w, v0, O[7][0]); O[7][1] = fmaf(pb.w, v1, O[7][1]);
            }
        }
        __syncthreads();
    }

    if (t < 64) sin_[t] = 1.f / ssum;
    __syncthreads();
#pragma unroll
    for (int j = 0; j < 8; j++) {
        const int qr = w * 8 + j;
        const float inv = sin_[qr];
        float* op = out + ((size_t)(s0 + qr) * H_ + hh) * HD_;
        op[lane]      = O[j][0] * inv;
        op[lane + 32] = O[j][1] * inv;
    }
}

// ---------------- global-query full attention: one block per (c, head) ----------------
__global__ __launch_bounds__(256) void glb_attn_kernel(
    const float* __restrict__ qg, const float* __restrict__ kg, const float* __restrict__ vg,
    const int* __restrict__ clss, const int* __restrict__ mask_src,
    float* __restrict__ out)
{
    const int c = blockIdx.x;
    const int h = blockIdx.y;
    __shared__ float qs[HD_];
    __shared__ float sc[S_];
    __shared__ float red[256];
    const int tid = threadIdx.x;
    const int lane = tid & 31;
    const int w = tid >> 5;

    if (tid < HD_) qs[tid] = qg[((size_t)c * H_ + h) * HD_ + tid] * 0.125f;
    __syncthreads();

    for (int p = w; p < S_; p += 8) {
        const float* kp = kg + ((size_t)p * H_ + h) * HD_;
        float sdot = qs[lane] * kp[lane] + qs[lane + 32] * kp[lane + 32];
#pragma unroll
        for (int o = 16; o > 0; o >>= 1) sdot += __shfl_xor_sync(0xffffffffu, sdot, o);
        if (lane == 0) sc[p] = (mask_src[p] > 0) ? sdot : -1e30f;
    }
    __syncthreads();

    float m = -1e30f;
    for (int p = tid; p < S_; p += 256) m = fmaxf(m, sc[p]);
    red[tid] = m; __syncthreads();
    for (int o = 128; o > 0; o >>= 1) { if (tid < o) red[tid] = fmaxf(red[tid], red[tid + o]); __syncthreads(); }
    m = red[0];
    __syncthreads();
    float sum = 0.f;
    for (int p = tid; p < S_; p += 256) { float e = __expf(sc[p] - m); sc[p] = e; sum += e; }
    red[tid] = sum; __syncthreads();
    for (int o = 128; o > 0; o >>= 1) { if (tid < o) red[tid] += red[tid + o]; __syncthreads(); }
    float inv = 1.f / red[0];
    __syncthreads();

    int d = tid & 63, quarter = tid >> 6;
    float acc = 0.f;
    for (int p = quarter; p < S_; p += 4)
        acc += sc[p] * vg[((size_t)p * H_ + h) * HD_ + d];
    red[tid] = acc; __syncthreads();
    if (tid < 64) {
        float o = (red[tid] + red[tid + 64] + red[tid + 128] + red[tid + 192]) * inv;
        int gp = clss[c];
        out[((size_t)gp * H_ + h) * HD_ + tid] = o;
    }
}

// ---------------- driver ----------------
static void run_gemm(const float* A, const float* B, const float* bias, float* C,
                     int M, int N, int K, int act)
{
    dim3 grid(N / 128, (M + 63) / 64);
    sgemm_kernel<<<grid, 128>>>(A, B, bias, C, M, N, K, act);
}

extern "C" void kernel_launch(void* const* d_in, const int* in_sizes, int n_in,
                              void* d_out, int out_size)
{
    (void)in_sizes; (void)n_in;
    const int*   x        = (const int*)d_in[0];
    const int*   mask_src = (const int*)d_in[1];
    const int*   clss     = (const int*)d_in[2];
    const int*   segs     = (const int*)d_in[3];
    const float* word_emb = (const float*)d_in[4];
    const float* pos_emb  = (const float*)d_in[5];
    const float* type_emb = (const float*)d_in[6];
    const float* ln_e_s   = (const float*)d_in[7];
    const float* ln_e_b   = (const float*)d_in[8];
    const float* Wq  = (const float*)d_in[9];   const float* bq  = (const float*)d_in[10];
    const float* Wk  = (const float*)d_in[11];  const float* bk  = (const float*)d_in[12];
    const float* Wv  = (const float*)d_in[13];  const float* bv  = (const float*)d_in[14];
    const float* Wqg = (const float*)d_in[15];  const float* bqg = (const float*)d_in[16];
    const float* Wkg = (const float*)d_in[17];  const float* bkg = (const float*)d_in[18];
    const float* Wvg = (const float*)d_in[19];  const float* bvg = (const float*)d_in[20];
    const float* Wo  = (const float*)d_in[21];  const float* bo  = (const float*)d_in[22];
    const float* ln1_s = (const float*)d_in[23]; const float* ln1_b = (const float*)d_in[24];
    const float* Wf1 = (const float*)d_in[25];  const float* bf1 = (const float*)d_in[26];
    const float* Wf2 = (const float*)d_in[27];  const float* bf2 = (const float*)d_in[28];
    const float* ln2_s = (const float*)d_in[29]; const float* ln2_b = (const float*)d_in[30];

    float *h, *q, *k, *v, *kg, *vg, *outb, *tmp, *ff, *hg, *qg;
    int* glb;
    cudaGetSymbolAddress((void**)&h,    g_h);
    cudaGetSymbolAddress((void**)&q,    g_q);
    cudaGetSymbolAddress((void**)&k,    g_k);
    cudaGetSymbolAddress((void**)&v,    g_v);
    cudaGetSymbolAddress((void**)&kg,   g_kg);
    cudaGetSymbolAddress((void**)&vg,   g_vg);
    cudaGetSymbolAddress((void**)&outb, g_out);
    cudaGetSymbolAddress((void**)&tmp,  g_tmp);
    cudaGetSymbolAddress((void**)&ff,   g_ff);
    cudaGetSymbolAddress((void**)&hg,   g_hg);
    cudaGetSymbolAddress((void**)&qg,   g_qg);
    cudaGetSymbolAddress((void**)&glb,  g_glb);

    cudaFuncSetAttribute(band_attn_tiled_kernel,
                         cudaFuncAttributeMaxDynamicSharedMemorySize, BAND_SMEM);

    // embedding + LN
    embed_ln_kernel<<<S_, 256>>>(x, segs, word_emb, pos_emb, type_emb, ln_e_s, ln_e_b, h);

    // global flags
    zero_flags_kernel<<<(S_ + 255) / 256, 256>>>(glb);
    set_flags_kernel<<<1, 64>>>(clss, glb);

    const size_t DD = (size_t)D_ * D_;
    for (int l = 0; l < LAYERS_; l++) {
        // Q K V Kg Vg projections: one batched launch (shared A = h)
        {
            GemmArgs ga;
            ga.B[0] = Wq  + l * DD; ga.bias[0] = bq  + l * D_; ga.C[0] = q;
            ga.B[1] = Wk  + l * DD; ga.bias[1] = bk  + l * D_; ga.C[1] = k;
            ga.B[2] = Wv  + l * DD; ga.bias[2] = bv  + l * D_; ga.C[2] = v;
            ga.B[3] = Wkg + l * DD; ga.bias[3] = bkg + l * D_; ga.C[3] = kg;
            ga.B[4] = Wvg + l * DD; ga.bias[4] = bvg + l * D_; ga.C[4] = vg;
            dim3 grid(D_ / 128, S_ / 64, NBAT_);
            sgemm_batched_kernel<<<grid, 128>>>(h, ga, S_, D_, D_);
        }

        // tiled band + global-key attention (writes all rows of outb)
        band_attn_tiled_kernel<<<dim3(S_ / 64, H_), 256, BAND_SMEM>>>(
            q, k, v, clss, mask_src, glb, outb);

        // global-query path
        gather_rows_kernel<<<NCLS_, 256>>>(h, clss, hg);
        run_gemm(hg, Wqg + l * DD, bqg + l * D_, qg, NCLS_, D_, D_, 0);
        glb_attn_kernel<<<dim3(NCLS_, H_), 256>>>(qg, kg, vg, clss, mask_src, outb);

        // output projection + residual LN
        run_gemm(outb, Wo + l * DD, bo + l * D_, tmp, S_, D_, D_, 0);
        add_ln_kernel<<<S_, 256>>>(h, tmp, ln1_s + l * D_, ln1_b + l * D_);

        // feed-forward
        run_gemm(h,  Wf1 + (size_t)l * D_ * FF_, bf1 + l * FF_, ff,  S_, FF_, D_, 1);
        run_gemm(ff, Wf2 + (size_t)l * D_ * FF_, bf2 + l * D_,  tmp, S_, D_, FF_, 0);
        add_ln_kernel<<<S_, 256>>>(h, tmp, ln2_s + l * D_, ln2_b + l * D_);
    }

    cudaMemcpyAsync(d_out, h, (size_t)out_size * sizeof(float), cudaMemcpyDeviceToDevice);
}

// round 17
// speedup vs baseline: 1.2327x; 1.0335x over previous
#include <cuda_runtime.h>
#include <math.h>
#include <stdint.h>

#define S_    4096
#define D_    768
#define H_    12
#define HD_   64
#define NCLS_ 64
#define FF_   3072
#define WIN_  256
#define LAYERS_ 2

typedef unsigned long long u64;

// ---------------- scratch (static device globals; no allocation) ----------------
__device__ float g_h  [S_*D_];
__device__ float g_q  [S_*D_];
__device__ float g_k  [S_*D_];
__device__ float g_v  [S_*D_];
__device__ float g_kg [S_*D_];
__device__ float g_vg [S_*D_];
__device__ float g_out[S_*D_];
__device__ float g_tmp[S_*D_];
__device__ float g_ff [S_*FF_];
__device__ float g_hg [NCLS_*D_];
__device__ float g_qg [NCLS_*D_];
__device__ int   g_glb[S_];

// ---------------- packed f32x2 helpers ----------------
static __device__ __forceinline__ u64 dup_f32x2(float x) {
    u64 r; asm("mov.b64 %0, {%1, %1};" : "=l"(r) : "f"(x)); return r;
}
static __device__ __forceinline__ void ffma2(u64& c, u64 a, u64 b) {
    asm("fma.rn.f32x2 %0, %1, %2, %0;" : "+l"(c) : "l"(a), "l"(b));
}
static __device__ __forceinline__ void unpack2(float& lo, float& hi, u64 v) {
    asm("mov.b64 {%0, %1}, %2;" : "=f"(lo), "=f"(hi) : "l"(v));
}

// ---------------- fp32 SGEMM core: 64x128 tile, 128 threads, BK=16 ----------------
#define BK_   16
#define SAS_  68
#define NBAT_ 6

#define LOADFRAG_(af, bfp, as, bs, kk)                                                        \
    *reinterpret_cast<float4*>(af)       = *reinterpret_cast<const float4*>((as) + (kk) * SAS_ + ty * 8);     \
    *reinterpret_cast<float4*>((af) + 4) = *reinterpret_cast<const float4*>((as) + (kk) * SAS_ + ty * 8 + 4); \
    *reinterpret_cast<ulonglong2*>(bfp)       = *reinterpret_cast<const ulonglong2*>((bs) + (kk) * 128 + tx * 8);     \
    *reinterpret_cast<ulonglong2*>((bfp) + 2) = *reinterpret_cast<const ulonglong2*>((bs) + (kk) * 128 + tx * 8 + 4);

#define FMA88_(af, bfp)                                      \
    _Pragma("unroll")                                        \
    for (int i_ = 0; i_ < 8; i_++) {                         \
        const u64 ad_ = dup_f32x2((af)[i_]);                 \
        _Pragma("unroll")                                    \
        for (int jp_ = 0; jp_ < 4; jp_++)                    \
            ffma2(acc2[i_][jp_], ad_, (bfp)[jp_]);           \
    }

struct GemmArgs {
    const float* A[NBAT_];
    const float* B[NBAT_];
    const float* bias[NBAT_];
    float*       C[NBAT_];
    int          M[NBAT_];
};

template <bool GELU>
static __device__ __forceinline__ void gemm_body(
    const float* __restrict__ A, const float* __restrict__ Bg,
    const float* __restrict__ bias, float* __restrict__ C,
    int M, int N, int K)
{
    __shared__ float As[2][BK_ * SAS_];
    __shared__ float Bs[2][BK_ * 128];
    const int tid = threadIdx.x;
    const int tx = tid & 15;
    const int ty = tid >> 4;
    const int blockRow = blockIdx.y * 64;
    const int blockCol = blockIdx.x * 128;
    const int aRow = tid >> 1;
    const int aCol = (tid & 1) * 8;
    const int bRow = tid >> 3;
    const int bCol = (tid & 7) * 16;

    u64 acc2[8][4];
#pragma unroll
    for (int i = 0; i < 8; i++)
#pragma unroll
        for (int jp = 0; jp < 4; jp++) acc2[i][jp] = 0ull;

    const float* Ap = A + (size_t)(blockRow + aRow) * K + aCol;
    const float* Bp = Bg + (size_t)bRow * N + blockCol + bCol;
    const bool aOk = (blockRow + aRow) < M;

    float4 pa0, pa1, pb[4];
    pa0 = make_float4(0.f, 0.f, 0.f, 0.f); pa1 = pa0;
    if (aOk) { pa0 = *reinterpret_cast<const float4*>(Ap);
               pa1 = *reinterpret_cast<const float4*>(Ap + 4); }
#pragma unroll
    for (int c = 0; c < 4; c++)
        pb[c] = *reinterpret_cast<const float4*>(Bp + c * 4);
    {
        float* as = As[0];
        as[(aCol + 0) * SAS_ + aRow] = pa0.x;
        as[(aCol + 1) * SAS_ + aRow] = pa0.y;
        as[(aCol + 2) * SAS_ + aRow] = pa0.z;
        as[(aCol + 3) * SAS_ + aRow] = pa0.w;
        as[(aCol + 4) * SAS_ + aRow] = pa1.x;
        as[(aCol + 5) * SAS_ + aRow] = pa1.y;
        as[(aCol + 6) * SAS_ + aRow] = pa1.z;
        as[(aCol + 7) * SAS_ + aRow] = pa1.w;
#pragma unroll
        for (int c = 0; c < 4; c++)
            *reinterpret_cast<float4*>(Bs[0] + bRow * 128 + bCol + c * 4) = pb[c];
    }
    __syncthreads();

    int s = 0;
    for (int k0 = BK_; k0 < K; k0 += BK_) {
        pa0 = make_float4(0.f, 0.f, 0.f, 0.f); pa1 = pa0;
        if (aOk) { pa0 = *reinterpret_cast<const float4*>(Ap + k0);
                   pa1 = *reinterpret_cast<const float4*>(Ap + k0 + 4); }
#pragma unroll
        for (int c = 0; c < 4; c++)
            pb[c] = *reinterpret_cast<const float4*>(Bp + (size_t)k0 * N + c * 4);

        {
            const float* as = As[s];
            const float* bs = Bs[s];
            float af[2][8];
            u64 bfp[2][4];
            LOADFRAG_(af[0], bfp[0], as, bs, 0);
#pragma unroll
            for (int kk = 0; kk < BK_; kk++) {
                const int cur = kk & 1;
                if (kk + 1 < BK_) {
                    LOADFRAG_(af[cur ^ 1], bfp[cur ^ 1], as, bs, kk + 1);
                }
                FMA88_(af[cur], bfp[cur]);
            }
        }

        float* asn = As[s ^ 1];
        asn[(aCol + 0) * SAS_ + aRow] = pa0.x;
        asn[(aCol + 1) * SAS_ + aRow] = pa0.y;
        asn[(aCol + 2) * SAS_ + aRow] = pa0.z;
        asn[(aCol + 3) * SAS_ + aRow] = pa0.w;
        asn[(aCol + 4) * SAS_ + aRow] = pa1.x;
        asn[(aCol + 5) * SAS_ + aRow] = pa1.y;
        asn[(aCol + 6) * SAS_ + aRow] = pa1.z;
        asn[(aCol + 7) * SAS_ + aRow] = pa1.w;
#pragma unroll
        for (int c = 0; c < 4; c++)
            *reinterpret_cast<float4*>(Bs[s ^ 1] + bRow * 128 + bCol + c * 4) = pb[c];
        __syncthreads();
        s ^= 1;
    }

    {
        const float* as = As[s];
        const float* bs = Bs[s];
        float af[2][8];
        u64 bfp[2][4];
        LOADFRAG_(af[0], bfp[0], as, bs, 0);
#pragma unroll
        for (int kk = 0; kk < BK_; kk++) {
            const int cur = kk & 1;
            if (kk + 1 < BK_) {
                LOADFRAG_(af[cur ^ 1], bfp[cur ^ 1], as, bs, kk + 1);
            }
            FMA88_(af[cur], bfp[cur]);
        }
    }

#pragma unroll
    for (int i = 0; i < 8; i++) {
        int r = blockRow + ty * 8 + i;
        if (r >= M) continue;
        float vals[8];
#pragma unroll
        for (int jp = 0; jp < 4; jp++) {
            float v0, v1;
            unpack2(v0, v1, acc2[i][jp]);
            vals[jp * 2 + 0] = v0;
            vals[jp * 2 + 1] = v1;
        }
#pragma unroll
        for (int j = 0; j < 8; j++) {
            int c = blockCol + tx * 8 + j;
            float val = vals[j] + bias[c];
            if (GELU) {
                float u = 0.7978845608028654f * (val + 0.044715f * val * val * val);
                float t = 1.f - 2.f / (__expf(2.f * u) + 1.f);
                val = 0.5f * val * (1.f + t);
            }
            vals[j] = val;
        }
        *reinterpret_cast<float4*>(C + (size_t)r * N + blockCol + tx * 8) =
            *reinterpret_cast<const float4*>(vals);
        *reinterpret_cast<float4*>(C + (size_t)r * N + blockCol + tx * 8 + 4) =
            *reinterpret_cast<const float4*>(vals + 4);
    }
}

__global__ __launch_bounds__(128, 4) void sgemm_kernel(
    const float* __restrict__ A, const float* __restrict__ B,
    const float* __restrict__ bias, float* __restrict__ C,
    int M, int N, int K, int act)
{
    if (act == 1) gemm_body<true>(A, B, bias, C, M, N, K);
    else          gemm_body<false>(A, B, bias, C, M, N, K);
}

// batched over blockIdx.z: C[z] = A[z] @ B[z] + bias[z]; rows beyond M[z] skipped
__global__ __launch_bounds__(128, 4) void sgemm_batched_kernel(
    GemmArgs args, int N, int K)
{
    const int z = blockIdx.z;
    const int M = args.M[z];
    if ((int)blockIdx.y * 64 >= M) return;
    gemm_body<false>(args.A[z], args.B[z], args.bias[z], args.C[z], M, N, K);
}

// ---------------- embedding + layernorm ----------------
__global__ __launch_bounds__(256) void embed_ln_kernel(
    const int* __restrict__ x, const int* __restrict__ segs,
    const float* __restrict__ we, const float* __restrict__ pe, const float* __restrict__ te,
    const float* __restrict__ lns, const float* __restrict__ lnb,
    float* __restrict__ hout)
{
    int s = blockIdx.x;
    int tid = threadIdx.x;
    __shared__ float buf[D_];
    __shared__ float red[256];
    int tok = x[s], seg = segs[s];
    float lsum = 0.f;
    for (int d = tid; d < D_; d += 256) {
        float v = we[(size_t)tok * D_ + d] + pe[(size_t)s * D_ + d] + te[(size_t)seg * D_ + d];
        buf[d] = v;
        lsum += v;
    }
    red[tid] = lsum; __syncthreads();
    for (int o = 128; o > 0; o >>= 1) { if (tid < o) red[tid] += red[tid + o]; __syncthreads(); }
    float mean = red[0] / D_;
    __syncthreads();
    float vsum = 0.f;
    for (int d = tid; d < D_; d += 256) { float t = buf[d] - mean; vsum += t * t; }
    red[tid] = vsum; __syncthreads();
    for (int o = 128; o > 0; o >>= 1) { if (tid < o) red[tid] += red[tid + o]; __syncthreads(); }
    float rstd = rsqrtf(red[0] / D_ + 1e-5f);
    for (int d = tid; d < D_; d += 256)
        hout[(size_t)s * D_ + d] = (buf[d] - mean) * rstd * lns[d] + lnb[d];
}

// ---------------- residual add + layernorm (in-place into h) ----------------
__global__ __launch_bounds__(256) void add_ln_kernel(
    float* __restrict__ h, const float* __restrict__ t,
    const float* __restrict__ lns, const float* __restrict__ lnb)
{
    int s = blockIdx.x;
    int tid = threadIdx.x;
    __shared__ float buf[D_];
    __shared__ float red[256];
    float lsum = 0.f;
    for (int d = tid; d < D_; d += 256) {
        float v = h[(size_t)s * D_ + d] + t[(size_t)s * D_ + d];
        buf[d] = v;
        lsum += v;
    }
    red[tid] = lsum; __syncthreads();
    for (int o = 128; o > 0; o >>= 1) { if (tid < o) red[tid] += red[tid + o]; __syncthreads(); }
    float mean = red[0] / D_;
    __syncthreads();
    float vsum = 0.f;
    for (int d = tid; d < D_; d += 256) { float x = buf[d] - mean; vsum += x * x; }
    red[tid] = vsum; __syncthreads();
    for (int o = 128; o > 0; o >>= 1) { if (tid < o) red[tid] += red[tid + o]; __syncthreads(); }
    float rstd = rsqrtf(red[0] / D_ + 1e-5f);
    for (int d = tid; d < D_; d += 256)
        h[(size_t)s * D_ + d] = (buf[d] - mean) * rstd * lns[d] + lnb[d];
}

// ---------------- global flags ----------------
__global__ void zero_flags_kernel(int* f)
{
    int i = blockIdx.x * 256 + threadIdx.x;
    if (i < S_) f[i] = 0;
}
__global__ void set_flags_kernel(const int* __restrict__ clss, int* f)
{
    if (threadIdx.x < NCLS_) f[clss[threadIdx.x]] = 1;
}
__global__ __launch_bounds__(256) void gather_rows_kernel(
    const float* __restrict__ h, const int* __restrict__ clss, float* __restrict__ hg)
{
    int c = blockIdx.x;
    int gp = clss[c];
    for (int d = threadIdx.x; d < D_; d += 256)
        hg[(size_t)c * D_ + d] = h[(size_t)gp * D_ + d];
}

// ================ tiled flash-style band + global-key attention ================
// One block per (64-query chunk, head). 640 keys = 64 global + 576 window,
// in 10 chunks of 64 keys. Online softmax parallelized 4 lanes/query.
#define BKEY_ 64
#define NCH_  10
#define KS_   68
#define VS_   68
#define PS_   72
#define OF_Q  0
#define OF_K  4096
#define OF_V  (OF_K + 64*KS_)
#define OF_P  (OF_V + BKEY_*VS_)
#define OF_KV (OF_P + BKEY_*PS_)
#define OF_SC (OF_KV + BKEY_)
#define OF_SI (OF_SC + 64)
#define OF_SM (OF_SI + 64)
#define OF_SS (OF_SM + 64)
#define BAND_SMEM ((OF_SS + 64) * 4)

__global__ __launch_bounds__(256) void band_attn_tiled_kernel(
    const float* __restrict__ q, const float* __restrict__ k, const float* __restrict__ v,
    const int* __restrict__ clss, const int* __restrict__ mask_src, const int* __restrict__ glb,
    float* __restrict__ out)
{
    extern __shared__ float sm[];
    float* Qsd = sm + OF_Q;          // [d][r]  stride 64
    float* Ksd = sm + OF_K;          // [d][kk] stride KS_
    float* Vs  = sm + OF_V;          // [kk][d] stride VS_
    float* Pkq = sm + OF_P;          // [kk][r] stride PS_
    int*   kvl = (int*)(sm + OF_KV);
    float* ssc  = sm + OF_SC;        // per-query rescale
    float* sin_ = sm + OF_SI;        // per-query 1/sum
    float* smx  = sm + OF_SM;        // running max
    float* ssm  = sm + OF_SS;        // running sum

    const int c = blockIdx.x, hh = blockIdx.y;
    const int s0 = c * 64;
    const int t = threadIdx.x;
    const int w = t >> 5, lane = t & 31;

    for (int idx = t; idx < 64 * 16; idx += 256) {
        const int r = idx >> 4, seg = (idx & 15) * 4;
        const float4 qv = *reinterpret_cast<const float4*>(
            q + ((size_t)(s0 + r) * H_ + hh) * HD_ + seg);
        Qsd[(seg + 0) * 64 + r] = qv.x * 0.125f;
        Qsd[(seg + 1) * 64 + r] = qv.y * 0.125f;
        Qsd[(seg + 2) * 64 + r] = qv.z * 0.125f;
        Qsd[(seg + 3) * 64 + r] = qv.w * 0.125f;
    }
    if (t < 64) { smx[t] = -1e30f; ssm[t] = 0.f; }

    float O[8][2];
#pragma unroll
    for (int j = 0; j < 8; j++) { O[j][0] = 0.f; O[j][1] = 0.f; }

    const int tq = t >> 3, tk = t & 7;   // 32 q-groups x 8 k-groups (QK phase)
    const int r0 = tq * 2, kk0 = tk * 8;
    const int qi = t >> 2, sub = t & 3;  // softmax: 4 lanes per query

    for (int ch = 0; ch < NCH_; ch++) {
        // ---- load K (transposed), V, validity : 64 keys ----
        for (int idx = t; idx < BKEY_ * 16; idx += 256) {
            const int kr = idx >> 4, seg = (idx & 15) * 4;
            const int gi = ch * BKEY_ + kr;
            int p; int val;
            if (gi < NCLS_) {
                p = clss[gi];
                val = (mask_src[p] > 0);
            } else {
                p = s0 + gi - 320;
                val = (p >= 0 && p < S_);
                if (val) val = (mask_src[p] > 0) && (glb[p] == 0);
                if (!val) p = 0;
            }
            if ((idx & 15) == 0) kvl[kr] = val;
            const float4 kv = *reinterpret_cast<const float4*>(
                k + ((size_t)p * H_ + hh) * HD_ + seg);
            Ksd[(seg + 0) * KS_ + kr] = kv.x;
            Ksd[(seg + 1) * KS_ + kr] = kv.y;
            Ksd[(seg + 2) * KS_ + kr] = kv.z;
            Ksd[(seg + 3) * KS_ + kr] = kv.w;
            *reinterpret_cast<float4*>(Vs + kr * VS_ + seg) =
                *reinterpret_cast<const float4*>(v + ((size_t)p * H_ + hh) * HD_ + seg);
        }
        __syncthreads();

        // ---- QK scores: thread computes 2q x 8k ----
        float sc[2][8];
#pragma unroll
        for (int j = 0; j < 2; j++)
#pragma unroll
            for (int i = 0; i < 8; i++) sc[j][i] = 0.f;
#pragma unroll 8
        for (int d = 0; d < 64; d++) {
            const float2 a = *reinterpret_cast<const float2*>(Qsd + d * 64 + r0);
            const float4 b0 = *reinterpret_cast<const float4*>(Ksd + d * KS_ + kk0);
            const float4 b1 = *reinterpret_cast<const float4*>(Ksd + d * KS_ + kk0 + 4);
            const float aa[2] = {a.x, a.y};
            const float bb[8] = {b0.x, b0.y, b0.z, b0.w, b1.x, b1.y, b1.z, b1.w};
#pragma unroll
            for (int j = 0; j < 2; j++)
#pragma unroll
                for (int i = 0; i < 8; i++) sc[j][i] = fmaf(aa[j], bb[i], sc[j][i]);
        }
#pragma unroll
        for (int i = 0; i < 8; i++) {
            const int gi = ch * BKEY_ + kk0 + i;
            const int kvalid = kvl[kk0 + i];
#pragma unroll
            for (int j = 0; j < 2; j++) {
                const int r = r0 + j;
                const bool ok = kvalid &&
                    (gi < NCLS_ || (r >= gi - 576 && r <= gi - 64));
                Pkq[(kk0 + i) * PS_ + r] = ok ? sc[j][i] : -1e30f;
            }
        }
        __syncthreads();

        // ---- online softmax: 4 lanes per query (each scans 16 keys) ----
        {
            float mn_p = -1e30f;
            for (int kk = sub; kk < BKEY_; kk += 4)
                mn_p = fmaxf(mn_p, Pkq[kk * PS_ + qi]);
            mn_p = fmaxf(mn_p, __shfl_xor_sync(0xffffffffu, mn_p, 1));
            mn_p = fmaxf(mn_p, __shfl_xor_sync(0xffffffffu, mn_p, 2));
            const float mold = smx[qi];
            const float mn = fmaxf(mold, mn_p);
            float ls = 0.f;
            for (int kk = sub; kk < BKEY_; kk += 4) {
                const float sv = Pkq[kk * PS_ + qi];
                const float pv = (sv <= -1e29f) ? 0.f : __expf(sv - mn);
                Pkq[kk * PS_ + qi] = pv;
                ls += pv;
            }
            ls += __shfl_xor_sync(0xffffffffu, ls, 1);
            ls += __shfl_xor_sync(0xffffffffu, ls, 2);
            if (sub == 0) {
                const float scale = (mn <= -1e29f) ? 1.f : __expf(mold - mn);
                ssm[qi] = ssm[qi] * scale + ls;
                smx[qi] = mn;
                ssc[qi] = scale;
            }
        }
        __syncthreads();

        // ---- PV accumulate: warp handles queries w*8..w*8+7, lane dims {lane, lane+32} ----
        {
#pragma unroll
            for (int j = 0; j < 8; j++) {
                const float scj = ssc[w * 8 + j];
                O[j][0] *= scj; O[j][1] *= scj;
            }
            for (int kk = 0; kk < BKEY_; kk++) {
                const float4 pa = *reinterpret_cast<const float4*>(Pkq + kk * PS_ + w * 8);
                const float4 pb = *reinterpret_cast<const float4*>(Pkq + kk * PS_ + w * 8 + 4);
                const float v0 = Vs[kk * VS_ + lane];
                const float v1 = Vs[kk * VS_ + lane + 32];
                O[0][0] = fmaf(pa.x, v0, O[0][0]); O[0][1] = fmaf(pa.x, v1, O[0][1]);
                O[1][0] = fmaf(pa.y, v0, O[1][0]); O[1][1] = fmaf(pa.y, v1, O[1][1]);
                O[2][0] = fmaf(pa.z, v0, O[2][0]); O[2][1] = fmaf(pa.z, v1, O[2][1]);
                O[3][0] = fmaf(pa.w, v0, O[3][0]); O[3][1] = fmaf(pa.w, v1, O[3][1]);
                O[4][0] = fmaf(pb.x, v0, O[4][0]); O[4][1] = fmaf(pb.x, v1, O[4][1]);
                O[5][0] = fmaf(pb.y, v0, O[5][0]); O[5][1] = fmaf(pb.y, v1, O[5][1]);
                O[6][0] = fmaf(pb.z, v0, O[6][0]); O[6][1] = fmaf(pb.z, v1, O[6][1]);
                O[7][0] = fmaf(pb.w, v0, O[7][0]); O[7][1] = fmaf(pb.w, v1, O[7][1]);
            }
        }
        __syncthreads();
    }

    if (t < 64) sin_[t] = 1.f / ssm[t];
    __syncthreads();
#pragma unroll
    for (int j = 0; j < 8; j++) {
        const int qr = w * 8 + j;
        const float inv = sin_[qr];
        float* op = out + ((size_t)(s0 + qr) * H_ + hh) * HD_;
        op[lane]      = O[j][0] * inv;
        op[lane + 32] = O[j][1] * inv;
    }
}

// ---------------- global-query full attention: one block per (c, head) ----------------
__global__ __launch_bounds__(256) void glb_attn_kernel(
    const float* __restrict__ qg, const float* __restrict__ kg, const float* __restrict__ vg,
    const int* __restrict__ clss, const int* __restrict__ mask_src,
    float* __restrict__ out)
{
    const int c = blockIdx.x;
    const int h = blockIdx.y;
    __shared__ float qs[HD_];
    __shared__ float sc[S_];
    __shared__ float red[256];
    const int tid = threadIdx.x;
    const int lane = tid & 31;
    const int w = tid >> 5;

    if (tid < HD_) qs[tid] = qg[((size_t)c * H_ + h) * HD_ + tid] * 0.125f;
    __syncthreads();

    for (int p = w; p < S_; p += 8) {
        const float* kp = kg + ((size_t)p * H_ + h) * HD_;
        float sdot = qs[lane] * kp[lane] + qs[lane + 32] * kp[lane + 32];
#pragma unroll
        for (int o = 16; o > 0; o >>= 1) sdot += __shfl_xor_sync(0xffffffffu, sdot, o);
        if (lane == 0) sc[p] = (mask_src[p] > 0) ? sdot : -1e30f;
    }
    __syncthreads();

    float m = -1e30f;
    for (int p = tid; p < S_; p += 256) m = fmaxf(m, sc[p]);
    red[tid] = m; __syncthreads();
    for (int o = 128; o > 0; o >>= 1) { if (tid < o) red[tid] = fmaxf(red[tid], red[tid + o]); __syncthreads(); }
    m = red[0];
    __syncthreads();
    float sum = 0.f;
    for (int p = tid; p < S_; p += 256) { float e = __expf(sc[p] - m); sc[p] = e; sum += e; }
    red[tid] = sum; __syncthreads();
    for (int o = 128; o > 0; o >>= 1) { if (tid < o) red[tid] += red[tid + o]; __syncthreads(); }
    float inv = 1.f / red[0];
    __syncthreads();

    int d = tid & 63, quarter = tid >> 6;
    float acc = 0.f;
    for (int p = quarter; p < S_; p += 4)
        acc += sc[p] * vg[((size_t)p * H_ + h) * HD_ + d];
    red[tid] = acc; __syncthreads();
    if (tid < 64) {
        float o = (red[tid] + red[tid + 64] + red[tid + 128] + red[tid + 192]) * inv;
        int gp = clss[c];
        out[((size_t)gp * H_ + h) * HD_ + tid] = o;
    }
}

// ---------------- driver ----------------
static void run_gemm(const float* A, const float* B, const float* bias, float* C,
                     int M, int N, int K, int act)
{
    dim3 grid(N / 128, (M + 63) / 64);
    sgemm_kernel<<<grid, 128>>>(A, B, bias, C, M, N, K, act);
}

extern "C" void kernel_launch(void* const* d_in, const int* in_sizes, int n_in,
                              void* d_out, int out_size)
{
    (void)in_sizes; (void)n_in;
    const int*   x        = (const int*)d_in[0];
    const int*   mask_src = (const int*)d_in[1];
    const int*   clss     = (const int*)d_in[2];
    const int*   segs     = (const int*)d_in[3];
    const float* word_emb = (const float*)d_in[4];
    const float* pos_emb  = (const float*)d_in[5];
    const float* type_emb = (const float*)d_in[6];
    const float* ln_e_s   = (const float*)d_in[7];
    const float* ln_e_b   = (const float*)d_in[8];
    const float* Wq  = (const float*)d_in[9];   const float* bq  = (const float*)d_in[10];
    const float* Wk  = (const float*)d_in[11];  const float* bk  = (const float*)d_in[12];
    const float* Wv  = (const float*)d_in[13];  const float* bv  = (const float*)d_in[14];
    const float* Wqg = (const float*)d_in[15];  const float* bqg = (const float*)d_in[16];
    const float* Wkg = (const float*)d_in[17];  const float* bkg = (const float*)d_in[18];
    const float* Wvg = (const float*)d_in[19];  const float* bvg = (const float*)d_in[20];
    const float* Wo  = (const float*)d_in[21];  const float* bo  = (const float*)d_in[22];
    const float* ln1_s = (const float*)d_in[23]; const float* ln1_b = (const float*)d_in[24];
    const float* Wf1 = (const float*)d_in[25];  const float* bf1 = (const float*)d_in[26];
    const float* Wf2 = (const float*)d_in[27];  const float* bf2 = (const float*)d_in[28];
    const float* ln2_s = (const float*)d_in[29]; const float* ln2_b = (const float*)d_in[30];

    float *h, *q, *k, *v, *kg, *vg, *outb, *tmp, *ff, *hg, *qg;
    int* glb;
    cudaGetSymbolAddress((void**)&h,    g_h);
    cudaGetSymbolAddress((void**)&q,    g_q);
    cudaGetSymbolAddress((void**)&k,    g_k);
    cudaGetSymbolAddress((void**)&v,    g_v);
    cudaGetSymbolAddress((void**)&kg,   g_kg);
    cudaGetSymbolAddress((void**)&vg,   g_vg);
    cudaGetSymbolAddress((void**)&outb, g_out);
    cudaGetSymbolAddress((void**)&tmp,  g_tmp);
    cudaGetSymbolAddress((void**)&ff,   g_ff);
    cudaGetSymbolAddress((void**)&hg,   g_hg);
    cudaGetSymbolAddress((void**)&qg,   g_qg);
    cudaGetSymbolAddress((void**)&glb,  g_glb);

    cudaFuncSetAttribute(band_attn_tiled_kernel,
                         cudaFuncAttributeMaxDynamicSharedMemorySize, BAND_SMEM);

    // embedding + LN
    embed_ln_kernel<<<S_, 256>>>(x, segs, word_emb, pos_emb, type_emb, ln_e_s, ln_e_b, h);

    // global flags
    zero_flags_kernel<<<(S_ + 255) / 256, 256>>>(glb);
    set_flags_kernel<<<1, 64>>>(clss, glb);

    const size_t DD = (size_t)D_ * D_;
    for (int l = 0; l < LAYERS_; l++) {
        // gather global rows (for qg projection)
        gather_rows_kernel<<<NCLS_, 256>>>(h, clss, hg);

        // Q K V Kg Vg Qg projections: one batched launch
        {
            GemmArgs ga;
            ga.A[0] = h;  ga.B[0] = Wq  + l * DD; ga.bias[0] = bq  + l * D_; ga.C[0] = q;  ga.M[0] = S_;
            ga.A[1] = h;  ga.B[1] = Wk  + l * DD; ga.bias[1] = bk  + l * D_; ga.C[1] = k;  ga.M[1] = S_;
            ga.A[2] = h;  ga.B[2] = Wv  + l * DD; ga.bias[2] = bv  + l * D_; ga.C[2] = v;  ga.M[2] = S_;
            ga.A[3] = h;  ga.B[3] = Wkg + l * DD; ga.bias[3] = bkg + l * D_; ga.C[3] = kg; ga.M[3] = S_;
            ga.A[4] = h;  ga.B[4] = Wvg + l * DD; ga.bias[4] = bvg + l * D_; ga.C[4] = vg; ga.M[4] = S_;
            ga.A[5] = hg; ga.B[5] = Wqg + l * DD; ga.bias[5] = bqg + l * D_; ga.C[5] = qg; ga.M[5] = NCLS_;
            dim3 grid(D_ / 128, S_ / 64, NBAT_);
            sgemm_batched_kernel<<<grid, 128>>>(ga, D_, D_);
        }

        // tiled band + global-key attention (writes all rows of outb)
        band_attn_tiled_kernel<<<dim3(S_ / 64, H_), 256, BAND_SMEM>>>(
            q, k, v, clss, mask_src, glb, outb);

        // global-query full attention (overwrites global rows)
        glb_attn_kernel<<<dim3(NCLS_, H_), 256>>>(qg, kg, vg, clss, mask_src, outb);

        // output projection + residual LN
        run_gemm(outb, Wo + l * DD, bo + l * D_, tmp, S_, D_, D_, 0);
        add_ln_kernel<<<S_, 256>>>(h, tmp, ln1_s + l * D_, ln1_b + l * D_);

        // feed-forward
        run_gemm(h,  Wf1 + (size_t)l * D_ * FF_, bf1 + l * FF_, ff,  S_, FF_, D_, 1);
        run_gemm(ff, Wf2 + (size_t)l * D_ * FF_, bf2 + l * D_,  tmp, S_, D_, FF_, 0);
        add_ln_kernel<<<S_, 256>>>(h, tmp, ln2_s + l * D_, ln2_b + l * D_);
    }

    cudaMemcpyAsync(d_out, h, (size_t)out_size * sizeof(float), cudaMemcpyDeviceToDevice);
}